// round 5
// baseline (speedup 1.0000x reference)
#include <cuda_runtime.h>
#include <cuda_bf16.h>
#include <cstdint>

// Problem constants
#define Bc 2
#define Sc 2048
#define Dc 1024
#define Hc 16
#define DKc 64
#define Mc (Bc*Sc)   // 4096

// ---------------- scratch (no allocations allowed) ----------------
__device__ __nv_bfloat16 g_Xh[3][Mc*Dc];
__device__ __nv_bfloat16 g_Xl[3][Mc*Dc];
__device__ __nv_bfloat16 g_Wh[4][Dc*Dc];
__device__ __nv_bfloat16 g_Wl[4][Dc*Dc];
__device__ __nv_bfloat16 g_Qh[Mc*Dc], g_Ql[Mc*Dc];
__device__ __nv_bfloat16 g_Kh[Mc*Dc], g_Kl[Mc*Dc];
__device__ __nv_bfloat16 g_Vh[Mc*Dc], g_Vl[Mc*Dc];
__device__ __nv_bfloat16 g_Ch[Mc*Dc], g_Cl[Mc*Dc];
__device__ float g_pm[Bc*Sc];
__device__ int   g_mask_mode;

// ---------------- helpers ----------------
__device__ __forceinline__ uint32_t smem_u32(const void* p) {
    return (uint32_t)__cvta_generic_to_shared(p);
}

#define MMA(c, a, b0, b1)                                                     \
    asm volatile(                                                             \
        "mma.sync.aligned.m16n8k16.row.col.f32.bf16.bf16.f32 "                \
        "{%0,%1,%2,%3},{%4,%5,%6,%7},{%8,%9},{%0,%1,%2,%3};\n"                \
        : "+f"((c)[0]), "+f"((c)[1]), "+f"((c)[2]), "+f"((c)[3])              \
        : "r"((a)[0]), "r"((a)[1]), "r"((a)[2]), "r"((a)[3]),                 \
          "r"(b0), "r"(b1));

#define LDMX4(r, addr)                                                        \
    asm volatile("ldmatrix.sync.aligned.m8n8.x4.shared.b16 {%0,%1,%2,%3}, [%4];" \
        : "=r"((r)[0]), "=r"((r)[1]), "=r"((r)[2]), "=r"((r)[3]) : "r"(addr));

#define LDMX4T(r, addr)                                                       \
    asm volatile("ldmatrix.sync.aligned.m8n8.x4.trans.shared.b16 {%0,%1,%2,%3}, [%4];" \
        : "=r"((r)[0]), "=r"((r)[1]), "=r"((r)[2]), "=r"((r)[3]) : "r"(addr));

#define CPA16(dst, src)                                                       \
    asm volatile("cp.async.cg.shared.global [%0], [%1], 16;\n"                \
        :: "r"(dst), "l"(src));
#define CPA_COMMIT() asm volatile("cp.async.commit_group;\n" ::: "memory")
#define CPA_WAIT0()  asm volatile("cp.async.wait_group 0;\n" ::: "memory")

__device__ __forceinline__ uint32_t packh2(float a, float b) {
    __nv_bfloat162 t;
    t.x = __float2bfloat16(a);
    t.y = __float2bfloat16(b);
    return *reinterpret_cast<uint32_t*>(&t);
}
__device__ __forceinline__ uint32_t packl2(float a, float b) {
    float ra = a - __bfloat162float(__float2bfloat16(a));
    float rb = b - __bfloat162float(__float2bfloat16(b));
    return packh2(ra, rb);
}

// ---------------- padding-mask dtype sniffing ----------------
__global__ void detect_mask_k(const unsigned int* __restrict__ mm) {
    __shared__ int okInt, okFloat;
    if (threadIdx.x == 0) { okInt = 1; okFloat = 1; }
    __syncthreads();
    for (int i = threadIdx.x; i < 1024; i += blockDim.x) {
        unsigned int v = mm[i];
        if (v > 1u) okInt = 0;
        if (v != 0u && v != 0x3F800000u) okFloat = 0;
    }
    __syncthreads();
    if (threadIdx.x == 0)
        g_mask_mode = okInt ? 1 : (okFloat ? 2 : 0);
}

__global__ void expand_mask_k(const void* __restrict__ mraw) {
    int i = blockIdx.x * blockDim.x + threadIdx.x;
    if (i >= Bc * Sc) return;
    int mode = g_mask_mode;
    float v;
    if (mode == 1)       v = (((const int*)mraw)[i] != 0) ? 1.f : 0.f;
    else if (mode == 2)  v = (((const float*)mraw)[i] != 0.f) ? 1.f : 0.f;
    else                 v = (((const unsigned char*)mraw)[i] != 0) ? 1.f : 0.f;
    g_pm[i] = v;
}

// ---------------- fp32 -> bf16 hi/lo split ----------------
__global__ void split_k(const float* __restrict__ x, int id, int n4) {
    int i = blockIdx.x * blockDim.x + threadIdx.x;
    if (i >= n4) return;
    __nv_bfloat16 *ph, *pl;
    if (id < 3) { ph = g_Xh[id]; pl = g_Xl[id]; }
    else        { ph = g_Wh[id - 3]; pl = g_Wl[id - 3]; }
    float4 v = ((const float4*)x)[i];
    float a[4] = {v.x, v.y, v.z, v.w};
    __nv_bfloat162 h0, h1, l0, l1;
    h0.x = __float2bfloat16(a[0]); h0.y = __float2bfloat16(a[1]);
    h1.x = __float2bfloat16(a[2]); h1.y = __float2bfloat16(a[3]);
    l0.x = __float2bfloat16(a[0] - __bfloat162float(h0.x));
    l0.y = __float2bfloat16(a[1] - __bfloat162float(h0.y));
    l1.x = __float2bfloat16(a[2] - __bfloat162float(h1.x));
    l1.y = __float2bfloat16(a[3] - __bfloat162float(h1.y));
    ((__nv_bfloat162*)ph)[i * 2]     = h0;
    ((__nv_bfloat162*)ph)[i * 2 + 1] = h1;
    ((__nv_bfloat162*)pl)[i * 2]     = l0;
    ((__nv_bfloat162*)pl)[i * 2 + 1] = l1;
}

// ---------------- bf16 split-GEMM, cp.async 2-stage, BK=16 ----------------
// 128x128 block tile, 8 warps (2x4).
// mode 0..2 (QKV): split bf16 out [B,H,S,DK]; mode 3: fp32 out [Mc,Dc]
struct GemmBias { const float* b[4]; };

#define ASTRIDE 24
#define BSTRIDE 136

__global__ __launch_bounds__(256) void gemm_k(GemmBias gb, int mode_in, float* Cf) {
    const int mode = (mode_in < 0) ? (int)blockIdx.z : mode_in;
    const __nv_bfloat16 *Ah, *Al, *Bh, *Bl;
    __nv_bfloat16 *Oh = nullptr, *Ol = nullptr;
    if (mode < 3) {
        Ah = g_Xh[mode]; Al = g_Xl[mode];
        Bh = g_Wh[mode]; Bl = g_Wl[mode];
        Oh = (mode == 0) ? g_Qh : (mode == 1) ? g_Kh : g_Vh;
        Ol = (mode == 0) ? g_Ql : (mode == 1) ? g_Kl : g_Vl;
    } else {
        Ah = g_Ch; Al = g_Cl; Bh = g_Wh[3]; Bl = g_Wl[3];
    }
    const float* bias = gb.b[mode];

    __shared__ __align__(16) __nv_bfloat16 sAh[2][128 * ASTRIDE], sAl[2][128 * ASTRIDE];
    __shared__ __align__(16) __nv_bfloat16 sBh[2][16 * BSTRIDE],  sBl[2][16 * BSTRIDE];

    const int tid = threadIdx.x;
    const int lane = tid & 31;
    const int wid = tid >> 5;
    const int wm = wid >> 2, wn = wid & 3;     // 2 x 4 warp grid
    const int g = lane >> 2, tg = lane & 3;
    const int sub = lane >> 3, rr = lane & 7;
    const int mBase = blockIdx.y * 128, nBase = blockIdx.x * 128;

    // per-thread cp.async coordinates
    const int arow = tid >> 1, ahalf = (tid & 1) * 8;          // A: 128x16, 16B each
    const int brow = tid >> 4, bcol = (tid & 15) * 8;          // B: 16x128, 16B each
    const uint32_t dAh0 = smem_u32(&sAh[0][arow * ASTRIDE + ahalf]);
    const uint32_t dAl0 = smem_u32(&sAl[0][arow * ASTRIDE + ahalf]);
    const uint32_t dBh0 = smem_u32(&sBh[0][brow * BSTRIDE + bcol]);
    const uint32_t dBl0 = smem_u32(&sBl[0][brow * BSTRIDE + bcol]);
    const uint32_t stA = (uint32_t)(128 * ASTRIDE * 2);
    const uint32_t stB = (uint32_t)(16 * BSTRIDE * 2);

#define GISSUE(kb, st)                                                         \
    {                                                                          \
        size_t aoff = (size_t)(mBase + arow) * Dc + (kb) * 16 + ahalf;         \
        size_t boff = (size_t)((kb) * 16 + brow) * Dc + nBase + bcol;          \
        CPA16(dAh0 + (st) * stA, Ah + aoff);                                   \
        CPA16(dAl0 + (st) * stA, Al + aoff);                                   \
        CPA16(dBh0 + (st) * stB, Bh + boff);                                   \
        CPA16(dBl0 + (st) * stB, Bl + boff);                                   \
        CPA_COMMIT();                                                          \
    }

    float acc[4][4][4];
#pragma unroll
    for (int i = 0; i < 4; i++)
#pragma unroll
        for (int j = 0; j < 4; j++)
#pragma unroll
            for (int k = 0; k < 4; k++) acc[i][j][k] = 0.f;

    GISSUE(0, 0);

    for (int kb = 0; kb < Dc / 16; kb++) {
        const int st = kb & 1;
        CPA_WAIT0();
        __syncthreads();
        if (kb + 1 < Dc / 16) GISSUE(kb + 1, st ^ 1);

        uint32_t fah[4][4], fal[4][4];
#pragma unroll
        for (int mf = 0; mf < 4; mf++) {
            int ar = wm * 64 + mf * 16 + (sub & 1) * 8 + rr;
            int ac = (sub >> 1) * 8;
            LDMX4(fah[mf], smem_u32(&sAh[st][ar * ASTRIDE + ac]));
            LDMX4(fal[mf], smem_u32(&sAl[st][ar * ASTRIDE + ac]));
        }
        uint32_t fbh[2][4], fbl[2][4];
#pragma unroll
        for (int nb = 0; nb < 2; nb++) {
            int br = (sub & 1) * 8 + rr;
            int bc = wn * 32 + nb * 16 + (sub >> 1) * 8;
            LDMX4T(fbh[nb], smem_u32(&sBh[st][br * BSTRIDE + bc]));
            LDMX4T(fbl[nb], smem_u32(&sBl[st][br * BSTRIDE + bc]));
        }
#pragma unroll
        for (int mf = 0; mf < 4; mf++)
#pragma unroll
            for (int nf = 0; nf < 4; nf++) {
                uint32_t b0h = fbh[nf >> 1][(nf & 1) * 2];
                uint32_t b1h = fbh[nf >> 1][(nf & 1) * 2 + 1];
                uint32_t b0l = fbl[nf >> 1][(nf & 1) * 2];
                uint32_t b1l = fbl[nf >> 1][(nf & 1) * 2 + 1];
                MMA(acc[mf][nf], fah[mf], b0h, b1h);
                MMA(acc[mf][nf], fah[mf], b0l, b1l);
                MMA(acc[mf][nf], fal[mf], b0h, b1h);
            }
        __syncthreads();
    }

    // epilogue
#pragma unroll
    for (int mf = 0; mf < 4; mf++) {
        int r0 = mBase + wm * 64 + mf * 16 + g;
        int r1 = r0 + 8;
#pragma unroll
        for (int nf = 0; nf < 4; nf++) {
            int n = nBase + wn * 32 + nf * 8 + tg * 2;
            float bv0 = bias[n], bv1 = bias[n + 1];
            float v00 = acc[mf][nf][0] + bv0, v01 = acc[mf][nf][1] + bv1;
            float v10 = acc[mf][nf][2] + bv0, v11 = acc[mf][nf][3] + bv1;
            if (mode == 3) {
                *(float2*)(Cf + (size_t)r0 * Dc + n) = make_float2(v00, v01);
                *(float2*)(Cf + (size_t)r1 * Dc + n) = make_float2(v10, v11);
            } else {
                int h = n >> 6, dk = n & 63;
#pragma unroll
                for (int p = 0; p < 2; p++) {
                    int r = p ? r1 : r0;
                    float a0 = p ? v10 : v00, a1 = p ? v11 : v01;
                    int b = r >> 11, s = r & 2047;
                    size_t idx = (((size_t)(b * Hc + h)) * Sc + s) * DKc + dk;
                    *(uint32_t*)(Oh + idx) = packh2(a0, a1);
                    *(uint32_t*)(Ol + idx) = packl2(a0, a1);
                }
            }
        }
    }
}

// ---------------- tensor-core flash attention ----------------
// CTA: one (b,h), 128 query rows; 8 warps x 16 rows. KV tile = 64 keys.
// Q A-fragments loaded directly from global (canonical m16n8k16 layout).
// Per-16-key streaming: score MMA -> mask+exp -> PV MMA (short live ranges).
// Masked score = 1e-10 (reference-faithful); scores bounded -> no max tracking.
__global__ __launch_bounds__(256) void attn_k() {
    __shared__ __align__(16) __nv_bfloat16 sKh[64 * 72], sKl[64 * 72];
    __shared__ __align__(16) __nv_bfloat16 sVh[64 * 72], sVl[64 * 72];
    __shared__ float pms[64];

    const int tid = threadIdx.x;
    const int lane = tid & 31;
    const int wid = tid >> 5;                 // 0..7
    const int g = lane >> 2, tg = lane & 3;
    const int sub = lane >> 3, rr = lane & 7;
    const int bh = blockIdx.y, b = bh >> 4, h = bh & 15;
    const int q0 = blockIdx.x * 128;
    const size_t base = (size_t)bh * Sc * DKc;

    const int row0 = q0 + wid * 16 + g, row1 = row0 + 8;

    // Q fragments straight from global memory
    uint32_t qh[4][4], ql[4][4];
    {
        const __nv_bfloat16* Qh = g_Qh + base;
        const __nv_bfloat16* Ql = g_Ql + base;
#pragma unroll
        for (int kb = 0; kb < 4; kb++) {
            int c0 = kb * 16 + 2 * tg;
            qh[kb][0] = *(const uint32_t*)(Qh + (size_t)row0 * DKc + c0);
            qh[kb][1] = *(const uint32_t*)(Qh + (size_t)row1 * DKc + c0);
            qh[kb][2] = *(const uint32_t*)(Qh + (size_t)row0 * DKc + c0 + 8);
            qh[kb][3] = *(const uint32_t*)(Qh + (size_t)row1 * DKc + c0 + 8);
            ql[kb][0] = *(const uint32_t*)(Ql + (size_t)row0 * DKc + c0);
            ql[kb][1] = *(const uint32_t*)(Ql + (size_t)row1 * DKc + c0);
            ql[kb][2] = *(const uint32_t*)(Ql + (size_t)row0 * DKc + c0 + 8);
            ql[kb][3] = *(const uint32_t*)(Ql + (size_t)row1 * DKc + c0 + 8);
        }
    }

    float o[8][4];
#pragma unroll
    for (int i = 0; i < 8; i++)
#pragma unroll
        for (int k = 0; k < 4; k++) o[i][k] = 0.f;
    float sum0 = 0.f, sum1 = 0.f;

    // cp.async coordinates: 64x64 bf16 per array = 512 16B chunks, 2/thread
    const int c0r = tid >> 3, c0c = (tid & 7) * 8;         // chunk tid
    const int c1r = (tid + 256) >> 3, c1c = c0c;           // chunk tid+256

    for (int kv0 = 0; kv0 < Sc; kv0 += 64) {
        __syncthreads();   // previous tile's compute done
        {
            size_t s0 = base + (size_t)(kv0 + c0r) * DKc + c0c;
            size_t s1 = base + (size_t)(kv0 + c1r) * DKc + c1c;
            uint32_t d0 = c0r * 72 + c0c, d1 = c1r * 72 + c1c;
            CPA16(smem_u32(sKh + d0), g_Kh + s0);
            CPA16(smem_u32(sKh + d1), g_Kh + s1);
            CPA16(smem_u32(sKl + d0), g_Kl + s0);
            CPA16(smem_u32(sKl + d1), g_Kl + s1);
            CPA16(smem_u32(sVh + d0), g_Vh + s0);
            CPA16(smem_u32(sVh + d1), g_Vh + s1);
            CPA16(smem_u32(sVl + d0), g_Vl + s0);
            CPA16(smem_u32(sVl + d1), g_Vl + s1);
            CPA_COMMIT();
        }
        if (tid < 64) pms[tid] = g_pm[b * Sc + kv0 + tid];
        CPA_WAIT0();
        __syncthreads();

#pragma unroll
        for (int t = 0; t < 4; t++) {   // 16 keys at a time
            float s0[4] = {0.f, 0.f, 0.f, 0.f};
            float s1[4] = {0.f, 0.f, 0.f, 0.f};
#pragma unroll
            for (int kb = 0; kb < 4; kb++) {
                uint32_t bKh[4], bKl[4];
                int krow = t * 16 + (sub >> 1) * 8 + rr;
                int kcol = kb * 16 + (sub & 1) * 8;
                LDMX4(bKh, smem_u32(sKh + krow * 72 + kcol));
                LDMX4(bKl, smem_u32(sKl + krow * 72 + kcol));
                MMA(s0, qh[kb], bKh[0], bKh[1]);
                MMA(s0, qh[kb], bKl[0], bKl[1]);
                MMA(s0, ql[kb], bKh[0], bKh[1]);
                MMA(s1, qh[kb], bKh[2], bKh[3]);
                MMA(s1, qh[kb], bKl[2], bKl[3]);
                MMA(s1, ql[kb], bKh[2], bKh[3]);
            }

            // mask + exp, pack as P A-fragment for this 16-key chunk
            uint32_t ph[4], pl[4];
            {
                int ka = kv0 + t * 16 + 2 * tg;        // keys of s0 pair
                int kb2 = ka + 8;                       // keys of s1 pair
                float2 mva = *(float2*)&pms[t * 16 + 2 * tg];
                float2 mvb = *(float2*)&pms[t * 16 + 8 + 2 * tg];
                float e00 = __expf((ka     > row0 || mva.x != 0.f) ? 1e-10f : s0[0] * 0.125f);
                float e01 = __expf((ka + 1 > row0 || mva.y != 0.f) ? 1e-10f : s0[1] * 0.125f);
                float e02 = __expf((ka     > row1 || mva.x != 0.f) ? 1e-10f : s0[2] * 0.125f);
                float e03 = __expf((ka + 1 > row1 || mva.y != 0.f) ? 1e-10f : s0[3] * 0.125f);
                float e10 = __expf((kb2     > row0 || mvb.x != 0.f) ? 1e-10f : s1[0] * 0.125f);
                float e11 = __expf((kb2 + 1 > row0 || mvb.y != 0.f) ? 1e-10f : s1[1] * 0.125f);
                float e12 = __expf((kb2     > row1 || mvb.x != 0.f) ? 1e-10f : s1[2] * 0.125f);
                float e13 = __expf((kb2 + 1 > row1 || mvb.y != 0.f) ? 1e-10f : s1[3] * 0.125f);
                sum0 += (e00 + e01) + (e10 + e11);
                sum1 += (e02 + e03) + (e12 + e13);
                ph[0] = packh2(e00, e01); ph[1] = packh2(e02, e03);
                ph[2] = packh2(e10, e11); ph[3] = packh2(e12, e13);
                pl[0] = packl2(e00, e01); pl[1] = packl2(e02, e03);
                pl[2] = packl2(e10, e11); pl[3] = packl2(e12, e13);
            }

            // O += P V for this 16-key chunk
#pragma unroll
            for (int dd = 0; dd < 4; dd++) {
                uint32_t vh_[4], vl_[4];
                int vrow = t * 16 + (sub & 1) * 8 + rr;
                int vcol = dd * 16 + (sub >> 1) * 8;
                LDMX4T(vh_, smem_u32(sVh + vrow * 72 + vcol));
                LDMX4T(vl_, smem_u32(sVl + vrow * 72 + vcol));
                MMA(o[2 * dd],     ph, vh_[0], vh_[1]);
                MMA(o[2 * dd],     ph, vl_[0], vl_[1]);
                MMA(o[2 * dd],     pl, vh_[0], vh_[1]);
                MMA(o[2 * dd + 1], ph, vh_[2], vh_[3]);
                MMA(o[2 * dd + 1], ph, vl_[2], vl_[3]);
                MMA(o[2 * dd + 1], pl, vh_[2], vh_[3]);
            }
        }
    }

    // rowsum reduce over the 4 lanes sharing a row
    sum0 += __shfl_xor_sync(0xFFFFFFFFu, sum0, 1);
    sum0 += __shfl_xor_sync(0xFFFFFFFFu, sum0, 2);
    sum1 += __shfl_xor_sync(0xFFFFFFFFu, sum1, 1);
    sum1 += __shfl_xor_sync(0xFFFFFFFFu, sum1, 2);
    float inv0 = 1.f / sum0, inv1 = 1.f / sum1;

#pragma unroll
    for (int nf = 0; nf < 8; nf++) {
        int dk = nf * 8 + tg * 2;
        float v00 = o[nf][0] * inv0, v01 = o[nf][1] * inv0;
        float v10 = o[nf][2] * inv1, v11 = o[nf][3] * inv1;
        size_t i0 = ((size_t)(b * Sc + row0)) * Dc + h * DKc + dk;
        size_t i1 = ((size_t)(b * Sc + row1)) * Dc + h * DKc + dk;
        *(uint32_t*)(g_Ch + i0) = packh2(v00, v01);
        *(uint32_t*)(g_Cl + i0) = packl2(v00, v01);
        *(uint32_t*)(g_Ch + i1) = packh2(v10, v11);
        *(uint32_t*)(g_Cl + i1) = packl2(v10, v11);
    }
}

// ---------------- launch ----------------
extern "C" void kernel_launch(void* const* d_in, const int* in_sizes, int n_in,
                              void* d_out, int out_size) {
    const float* query = (const float*)d_in[0];
    const float* key   = (const float*)d_in[1];
    const float* value = (const float*)d_in[2];
    const void*  pmask = d_in[3];
    const float* Wq = (const float*)d_in[4];
    const float* bq = (const float*)d_in[5];
    const float* Wk = (const float*)d_in[6];
    const float* bk = (const float*)d_in[7];
    const float* Wv = (const float*)d_in[8];
    const float* bv = (const float*)d_in[9];
    const float* Wo = (const float*)d_in[10];
    const float* bo = (const float*)d_in[11];
    float* out = (float*)d_out;

    detect_mask_k<<<1, 256>>>((const unsigned int*)pmask);
    expand_mask_k<<<(Bc * Sc + 255) / 256, 256>>>(pmask);

    const int nAct4 = Mc * Dc / 4;
    const int nW4   = Dc * Dc / 4;
    split_k<<<(nAct4 + 255) / 256, 256>>>(query, 0, nAct4);
    split_k<<<(nAct4 + 255) / 256, 256>>>(key,   1, nAct4);
    split_k<<<(nAct4 + 255) / 256, 256>>>(value, 2, nAct4);
    split_k<<<(nW4 + 255) / 256, 256>>>(Wq, 3, nW4);
    split_k<<<(nW4 + 255) / 256, 256>>>(Wk, 4, nW4);
    split_k<<<(nW4 + 255) / 256, 256>>>(Wv, 5, nW4);
    split_k<<<(nW4 + 255) / 256, 256>>>(Wo, 6, nW4);

    GemmBias gb;
    gb.b[0] = bq; gb.b[1] = bk; gb.b[2] = bv; gb.b[3] = bo;

    dim3 gQKV(Dc / 128, Mc / 128, 3);   // (8, 32, 3)
    gemm_k<<<gQKV, 256>>>(gb, -1, nullptr);

    dim3 gAttn(Sc / 128, Bc * Hc);      // (16, 32)
    attn_k<<<gAttn, 256>>>();

    dim3 gOut(Dc / 128, Mc / 128);      // (8, 32)
    gemm_k<<<gOut, 256>>>(gb, 3, out);
}

// round 8
// speedup vs baseline: 1.0582x; 1.0582x over previous
#include <cuda_runtime.h>
#include <cuda_bf16.h>
#include <cstdint>

// Problem constants
#define Bc 2
#define Sc 2048
#define Dc 1024
#define Hc 16
#define DKc 64
#define Mc (Bc*Sc)   // 4096
#define NTILES 32    // Sc / 64

// ---------------- scratch (no allocations allowed) ----------------
__device__ __nv_bfloat16 g_Xh[3][Mc*Dc];
__device__ __nv_bfloat16 g_Xl[3][Mc*Dc];
__device__ __nv_bfloat16 g_Wh[4][Dc*Dc];
__device__ __nv_bfloat16 g_Wl[4][Dc*Dc];
__device__ __nv_bfloat16 g_Qh[Mc*Dc], g_Ql[Mc*Dc];
__device__ __nv_bfloat16 g_Kh[Mc*Dc], g_Kl[Mc*Dc];
__device__ __nv_bfloat16 g_Vh[Mc*Dc], g_Vl[Mc*Dc];
__device__ __nv_bfloat16 g_Ch[Mc*Dc], g_Cl[Mc*Dc];
__device__ float g_Vsuf[Bc*Hc*(NTILES+1)*DKc];   // fp32 V suffix sums per tile boundary
__device__ float g_pm[Bc*Sc];
__device__ int   g_mask_mode;

// ---------------- helpers ----------------
__device__ __forceinline__ uint32_t smem_u32(const void* p) {
    return (uint32_t)__cvta_generic_to_shared(p);
}

#define MMA(c, a, b0, b1)                                                     \
    asm volatile(                                                             \
        "mma.sync.aligned.m16n8k16.row.col.f32.bf16.bf16.f32 "                \
        "{%0,%1,%2,%3},{%4,%5,%6,%7},{%8,%9},{%0,%1,%2,%3};\n"                \
        : "+f"((c)[0]), "+f"((c)[1]), "+f"((c)[2]), "+f"((c)[3])              \
        : "r"((a)[0]), "r"((a)[1]), "r"((a)[2]), "r"((a)[3]),                 \
          "r"(b0), "r"(b1));

#define LDMX4(r, addr)                                                        \
    asm volatile("ldmatrix.sync.aligned.m8n8.x4.shared.b16 {%0,%1,%2,%3}, [%4];" \
        : "=r"((r)[0]), "=r"((r)[1]), "=r"((r)[2]), "=r"((r)[3]) : "r"(addr));

#define LDMX4T(r, addr)                                                       \
    asm volatile("ldmatrix.sync.aligned.m8n8.x4.trans.shared.b16 {%0,%1,%2,%3}, [%4];" \
        : "=r"((r)[0]), "=r"((r)[1]), "=r"((r)[2]), "=r"((r)[3]) : "r"(addr));

__device__ __forceinline__ uint32_t packh2(float a, float b) {
    __nv_bfloat162 t;
    t.x = __float2bfloat16(a);
    t.y = __float2bfloat16(b);
    return *reinterpret_cast<uint32_t*>(&t);
}
__device__ __forceinline__ uint32_t packl2(float a, float b) {
    float ra = a - __bfloat162float(__float2bfloat16(a));
    float rb = b - __bfloat162float(__float2bfloat16(b));
    return packh2(ra, rb);
}

// ---------------- padding-mask dtype sniffing ----------------
__global__ void detect_mask_k(const unsigned int* __restrict__ mm) {
    __shared__ int okInt, okFloat;
    if (threadIdx.x == 0) { okInt = 1; okFloat = 1; }
    __syncthreads();
    for (int i = threadIdx.x; i < 1024; i += blockDim.x) {
        unsigned int v = mm[i];
        if (v > 1u) okInt = 0;
        if (v != 0u && v != 0x3F800000u) okFloat = 0;
    }
    __syncthreads();
    if (threadIdx.x == 0)
        g_mask_mode = okInt ? 1 : (okFloat ? 2 : 0);
}

__global__ void expand_mask_k(const void* __restrict__ mraw) {
    int i = blockIdx.x * blockDim.x + threadIdx.x;
    if (i >= Bc * Sc) return;
    int mode = g_mask_mode;
    float v;
    if (mode == 1)       v = (((const int*)mraw)[i] != 0) ? 1.f : 0.f;
    else if (mode == 2)  v = (((const float*)mraw)[i] != 0.f) ? 1.f : 0.f;
    else                 v = (((const unsigned char*)mraw)[i] != 0) ? 1.f : 0.f;
    g_pm[i] = v;
}

// ---------------- fp32 -> bf16 hi/lo split (all 7 tensors, one launch) ----------------
struct SplitArgs { const float* src[7]; };

__global__ void split_all_k(SplitArgs sa) {
    const int id = blockIdx.y;
    const int n4 = (id < 3) ? (Mc * Dc / 4) : (Dc * Dc / 4);
    int i = blockIdx.x * blockDim.x + threadIdx.x;
    if (i >= n4) return;
    __nv_bfloat16 *ph, *pl;
    if (id < 3) { ph = g_Xh[id]; pl = g_Xl[id]; }
    else        { ph = g_Wh[id - 3]; pl = g_Wl[id - 3]; }
    float4 v = ((const float4*)sa.src[id])[i];
    float a[4] = {v.x, v.y, v.z, v.w};
    __nv_bfloat162 h0, h1, l0, l1;
    h0.x = __float2bfloat16(a[0]); h0.y = __float2bfloat16(a[1]);
    h1.x = __float2bfloat16(a[2]); h1.y = __float2bfloat16(a[3]);
    l0.x = __float2bfloat16(a[0] - __bfloat162float(h0.x));
    l0.y = __float2bfloat16(a[1] - __bfloat162float(h0.y));
    l1.x = __float2bfloat16(a[2] - __bfloat162float(h1.x));
    l1.y = __float2bfloat16(a[3] - __bfloat162float(h1.y));
    ((__nv_bfloat162*)ph)[i * 2]     = h0;
    ((__nv_bfloat162*)ph)[i * 2 + 1] = h1;
    ((__nv_bfloat162*)pl)[i * 2]     = l0;
    ((__nv_bfloat162*)pl)[i * 2 + 1] = l1;
}

// ---------------- V suffix sums (fp32) ----------------
// Vsuf[bh][t][dk] = sum_{j >= t*64} V[bh, j, dk]; Vsuf[bh][NTILES] = 0.
__global__ void vsuffix_k() {
    const int bh = blockIdx.x;
    const int dk = threadIdx.x;
    const size_t base = (size_t)bh * Sc * DKc + dk;
    float* out = g_Vsuf + ((size_t)bh * (NTILES + 1)) * DKc + dk;
    float acc = 0.f;
    out[NTILES * DKc] = 0.f;
    for (int t = NTILES - 1; t >= 0; t--) {
        float part = 0.f;
#pragma unroll 16
        for (int j = 0; j < 64; j++) {
            size_t idx = base + (size_t)(t * 64 + j) * DKc;
            part += __bfloat162float(g_Vh[idx]) + __bfloat162float(g_Vl[idx]);
        }
        acc += part;
        out[t * DKc] = acc;
    }
}

// ---------------- bf16 split-GEMM (R3-proven): 128x128x32, 8 warps ----------------
struct GemmBias { const float* b[4]; };

__global__ __launch_bounds__(256) void gemm_k(GemmBias gb, int mode_in, float* Cf) {
    const int mode = (mode_in < 0) ? (int)blockIdx.z : mode_in;
    const __nv_bfloat16 *Ah, *Al, *Bh, *Bl;
    __nv_bfloat16 *Oh = nullptr, *Ol = nullptr;
    if (mode < 3) {
        Ah = g_Xh[mode]; Al = g_Xl[mode];
        Bh = g_Wh[mode]; Bl = g_Wl[mode];
        Oh = (mode == 0) ? g_Qh : (mode == 1) ? g_Kh : g_Vh;
        Ol = (mode == 0) ? g_Ql : (mode == 1) ? g_Kl : g_Vl;
    } else {
        Ah = g_Ch; Al = g_Cl; Bh = g_Wh[3]; Bl = g_Wl[3];
    }
    const float* bias = gb.b[mode];

    __shared__ __align__(16) __nv_bfloat16 sAh[128 * 56], sAl[128 * 56];
    __shared__ __align__(16) __nv_bfloat16 sBh[32 * 136], sBl[32 * 136];

    const int tid = threadIdx.x;
    const int lane = tid & 31;
    const int wid = tid >> 5;
    const int wm = wid >> 2, wn = wid & 3;
    const int g = lane >> 2, tg = lane & 3;
    const int sub = lane >> 3, rr = lane & 7;
    const int mBase = blockIdx.y * 128, nBase = blockIdx.x * 128;

    float acc[4][4][4];
#pragma unroll
    for (int i = 0; i < 4; i++)
#pragma unroll
        for (int j = 0; j < 4; j++)
#pragma unroll
            for (int k = 0; k < 4; k++) acc[i][j][k] = 0.f;

    uint4 ra[2], ral[2], rb[2], rbl[2];

#define GLOAD(kb)                                                              \
    {                                                                          \
        _Pragma("unroll")                                                      \
        for (int i = 0; i < 2; i++) {                                          \
            int c = tid * 2 + i;                                               \
            int arow = c >> 2, acol = (c & 3) * 8;                             \
            size_t aoff = (size_t)(mBase + arow) * Dc + (kb) * 32 + acol;      \
            ra[i]  = *(const uint4*)(Ah + aoff);                               \
            ral[i] = *(const uint4*)(Al + aoff);                               \
            int brow = c >> 4, bcol = (c & 15) * 8;                            \
            size_t boff = (size_t)((kb) * 32 + brow) * Dc + nBase + bcol;      \
            rb[i]  = *(const uint4*)(Bh + boff);                               \
            rbl[i] = *(const uint4*)(Bl + boff);                               \
        }                                                                      \
    }

    GLOAD(0);
    for (int kb = 0; kb < Dc / 32; kb++) {
        __syncthreads();
#pragma unroll
        for (int i = 0; i < 2; i++) {
            int c = tid * 2 + i;
            int arow = c >> 2, acol = (c & 3) * 8;
            *(uint4*)(sAh + arow * 56 + acol) = ra[i];
            *(uint4*)(sAl + arow * 56 + acol) = ral[i];
            int brow = c >> 4, bcol = (c & 15) * 8;
            *(uint4*)(sBh + brow * 136 + bcol) = rb[i];
            *(uint4*)(sBl + brow * 136 + bcol) = rbl[i];
        }
        __syncthreads();
        if (kb + 1 < Dc / 32) GLOAD(kb + 1);

#pragma unroll
        for (int ks = 0; ks < 2; ks++) {
            uint32_t fah[4][4], fal[4][4];
#pragma unroll
            for (int mf = 0; mf < 4; mf++) {
                int arow = wm * 64 + mf * 16 + (sub & 1) * 8 + rr;
                int acol = ks * 16 + (sub >> 1) * 8;
                LDMX4(fah[mf], smem_u32(sAh + arow * 56 + acol));
                LDMX4(fal[mf], smem_u32(sAl + arow * 56 + acol));
            }
            uint32_t fbh[2][4], fbl[2][4];
#pragma unroll
            for (int nb = 0; nb < 2; nb++) {
                int brow = ks * 16 + (sub & 1) * 8 + rr;
                int bcol = wn * 32 + nb * 16 + (sub >> 1) * 8;
                LDMX4T(fbh[nb], smem_u32(sBh + brow * 136 + bcol));
                LDMX4T(fbl[nb], smem_u32(sBl + brow * 136 + bcol));
            }
#pragma unroll
            for (int mf = 0; mf < 4; mf++)
#pragma unroll
                for (int nf = 0; nf < 4; nf++) {
                    uint32_t b0h = fbh[nf >> 1][(nf & 1) * 2];
                    uint32_t b1h = fbh[nf >> 1][(nf & 1) * 2 + 1];
                    uint32_t b0l = fbl[nf >> 1][(nf & 1) * 2];
                    uint32_t b1l = fbl[nf >> 1][(nf & 1) * 2 + 1];
                    MMA(acc[mf][nf], fah[mf], b0h, b1h);
                    MMA(acc[mf][nf], fah[mf], b0l, b1l);
                    MMA(acc[mf][nf], fal[mf], b0h, b1h);
                }
        }
    }

    // epilogue
#pragma unroll
    for (int mf = 0; mf < 4; mf++) {
        int r0 = mBase + wm * 64 + mf * 16 + g;
        int r1 = r0 + 8;
#pragma unroll
        for (int nf = 0; nf < 4; nf++) {
            int n = nBase + wn * 32 + nf * 8 + tg * 2;
            float bv0 = bias[n], bv1 = bias[n + 1];
            float v00 = acc[mf][nf][0] + bv0, v01 = acc[mf][nf][1] + bv1;
            float v10 = acc[mf][nf][2] + bv0, v11 = acc[mf][nf][3] + bv1;
            if (mode == 3) {
                *(float2*)(Cf + (size_t)r0 * Dc + n) = make_float2(v00, v01);
                *(float2*)(Cf + (size_t)r1 * Dc + n) = make_float2(v10, v11);
            } else {
                int h = n >> 6, dk = n & 63;
#pragma unroll
                for (int p = 0; p < 2; p++) {
                    int r = p ? r1 : r0;
                    float a0 = p ? v10 : v00, a1 = p ? v11 : v01;
                    int b = r >> 11, s = r & 2047;
                    size_t idx = (((size_t)(b * Hc + h)) * Sc + s) * DKc + dk;
                    *(uint32_t*)(Oh + idx) = packh2(a0, a1);
                    *(uint32_t*)(Ol + idx) = packl2(a0, a1);
                }
            }
        }
    }
}

// ---------------- tensor-core flash attention + suffix-sum skipping ----------------
// Masked score = 1e-10 -> masked weight is EXACTLY exp(1e-10)=1.0f, so any
// fully-future tile contributes (sum_j v_j, count) -- precomputed in g_Vsuf.
// Only tiles kv0 <= q_max get MMAs (48.4% of tile work eliminated).
// NOTE: the future-key count is added AFTER the 4-lane rowsum reduction
// (the per-lane sums are partial; adding before reduction counted it 4x).
__global__ __launch_bounds__(128) void attn_k() {
    __shared__ __align__(16) __nv_bfloat16 sKh[64 * 72], sKl[64 * 72];
    __shared__ __align__(16) __nv_bfloat16 sVh[64 * 72], sVl[64 * 72];
    __shared__ float pms[64];

    const int tid = threadIdx.x;
    const int lane = tid & 31;
    const int wid = tid >> 5;
    const int g = lane >> 2, tg = lane & 3;
    const int sub = lane >> 3, rr = lane & 7;
    const int bh = blockIdx.y, b = bh >> 4, h = bh & 15;
    const int qblk = (int)gridDim.x - 1 - (int)blockIdx.x;   // longest CTAs first
    const int q0 = qblk * 64;
    const int nT = qblk + 1;                                  // tiles needing MMA
    const size_t base = (size_t)bh * Sc * DKc;

    // stage Q through sK buffers, extract A-fragments to registers
    uint32_t qh[4][4], ql[4][4];
    for (int c = tid; c < 64 * 8; c += 128) {
        int row = c >> 3, col = (c & 7) * 8;
        size_t off = base + (size_t)(q0 + row) * DKc + col;
        *(uint4*)(sKh + row * 72 + col) = *(const uint4*)(g_Qh + off);
        *(uint4*)(sKl + row * 72 + col) = *(const uint4*)(g_Ql + off);
    }
    __syncthreads();
#pragma unroll
    for (int kb = 0; kb < 4; kb++) {
        int arow = wid * 16 + (sub & 1) * 8 + rr;
        int acol = kb * 16 + (sub >> 1) * 8;
        LDMX4(qh[kb], smem_u32(sKh + arow * 72 + acol));
        LDMX4(ql[kb], smem_u32(sKl + arow * 72 + acol));
    }

    float o[8][4];
#pragma unroll
    for (int i = 0; i < 8; i++)
#pragma unroll
        for (int k = 0; k < 4; k++) o[i][k] = 0.f;
    float sum0 = 0.f, sum1 = 0.f;
    const int row0 = q0 + wid * 16 + g, row1 = row0 + 8;

    for (int kv0 = 0; kv0 < nT * 64; kv0 += 64) {
        __syncthreads();
        for (int c = tid; c < 64 * 8; c += 128) {
            int row = c >> 3, col = (c & 7) * 8;
            size_t off = base + (size_t)(kv0 + row) * DKc + col;
            *(uint4*)(sKh + row * 72 + col) = *(const uint4*)(g_Kh + off);
            *(uint4*)(sKl + row * 72 + col) = *(const uint4*)(g_Kl + off);
            *(uint4*)(sVh + row * 72 + col) = *(const uint4*)(g_Vh + off);
            *(uint4*)(sVl + row * 72 + col) = *(const uint4*)(g_Vl + off);
        }
        if (tid < 64) pms[tid] = g_pm[b * Sc + kv0 + tid];
        __syncthreads();

        // S = Q K^T  (split, 3-term)
        float s[8][4];
#pragma unroll
        for (int i = 0; i < 8; i++)
#pragma unroll
            for (int k = 0; k < 4; k++) s[i][k] = 0.f;
#pragma unroll
        for (int jj = 0; jj < 4; jj++) {
#pragma unroll
            for (int kb = 0; kb < 4; kb++) {
                uint32_t bKh[4], bKl[4];
                int krow = jj * 16 + (sub >> 1) * 8 + rr;
                int kcol = kb * 16 + (sub & 1) * 8;
                LDMX4(bKh, smem_u32(sKh + krow * 72 + kcol));
                LDMX4(bKl, smem_u32(sKl + krow * 72 + kcol));
                MMA(s[2 * jj],     qh[kb], bKh[0], bKh[1]);
                MMA(s[2 * jj],     qh[kb], bKl[0], bKl[1]);
                MMA(s[2 * jj],     ql[kb], bKh[0], bKh[1]);
                MMA(s[2 * jj + 1], qh[kb], bKh[2], bKh[3]);
                MMA(s[2 * jj + 1], qh[kb], bKl[2], bKl[3]);
                MMA(s[2 * jj + 1], ql[kb], bKh[2], bKh[3]);
            }
        }

        // mask + exp, re-pack as P A-fragments
        uint32_t ph[4][4], pl[4][4];
#pragma unroll
        for (int j = 0; j < 8; j++) {
            int cg = kv0 + j * 8 + tg * 2;
            float2 mv = *(float2*)&pms[j * 8 + tg * 2];
            float sc0 = (cg     > row0 || mv.x != 0.f) ? 1e-10f : s[j][0] * 0.125f;
            float sc1 = (cg + 1 > row0 || mv.y != 0.f) ? 1e-10f : s[j][1] * 0.125f;
            float sc2 = (cg     > row1 || mv.x != 0.f) ? 1e-10f : s[j][2] * 0.125f;
            float sc3 = (cg + 1 > row1 || mv.y != 0.f) ? 1e-10f : s[j][3] * 0.125f;
            float e0 = __expf(sc0), e1 = __expf(sc1);
            float e2 = __expf(sc2), e3 = __expf(sc3);
            sum0 += e0 + e1;
            sum1 += e2 + e3;
            int t = j >> 1;
            if ((j & 1) == 0) {
                ph[t][0] = packh2(e0, e1); ph[t][1] = packh2(e2, e3);
                pl[t][0] = packl2(e0, e1); pl[t][1] = packl2(e2, e3);
            } else {
                ph[t][2] = packh2(e0, e1); ph[t][3] = packh2(e2, e3);
                pl[t][2] = packl2(e0, e1); pl[t][3] = packl2(e2, e3);
            }
        }

        // O += P V  (split, 3-term)
#pragma unroll
        for (int dd = 0; dd < 4; dd++) {
#pragma unroll
            for (int t = 0; t < 4; t++) {
                uint32_t vh_[4], vl_[4];
                int vrow = t * 16 + (sub & 1) * 8 + rr;
                int vcol = dd * 16 + (sub >> 1) * 8;
                LDMX4T(vh_, smem_u32(sVh + vrow * 72 + vcol));
                LDMX4T(vl_, smem_u32(sVl + vrow * 72 + vcol));
                MMA(o[2 * dd],     ph[t], vh_[0], vh_[1]);
                MMA(o[2 * dd],     ph[t], vl_[0], vl_[1]);
                MMA(o[2 * dd],     pl[t], vh_[0], vh_[1]);
                MMA(o[2 * dd + 1], ph[t], vh_[2], vh_[3]);
                MMA(o[2 * dd + 1], ph[t], vl_[2], vl_[3]);
                MMA(o[2 * dd + 1], pl[t], vh_[2], vh_[3]);
            }
        }
    }

    // future keys: per-lane-owned o elements get the fp32 suffix sum
    {
        const float* suf = g_Vsuf + ((size_t)bh * (NTILES + 1) + nT) * DKc;
#pragma unroll
        for (int nf = 0; nf < 8; nf++) {
            int col = nf * 8 + tg * 2;
            float vA = suf[col], vB = suf[col + 1];
            o[nf][0] += vA; o[nf][1] += vB;
            o[nf][2] += vA; o[nf][3] += vB;
        }
    }

    // rowsum reduce over the 4 lanes sharing a row, THEN add future-key count once
    sum0 += __shfl_xor_sync(0xFFFFFFFFu, sum0, 1);
    sum0 += __shfl_xor_sync(0xFFFFFFFFu, sum0, 2);
    sum1 += __shfl_xor_sync(0xFFFFFFFFu, sum1, 1);
    sum1 += __shfl_xor_sync(0xFFFFFFFFu, sum1, 2);
    const float cnt = (float)(Sc - nT * 64);
    sum0 += cnt;
    sum1 += cnt;
    float inv0 = 1.f / sum0, inv1 = 1.f / sum1;

#pragma unroll
    for (int nf = 0; nf < 8; nf++) {
        int dk = nf * 8 + tg * 2;
        float v00 = o[nf][0] * inv0, v01 = o[nf][1] * inv0;
        float v10 = o[nf][2] * inv1, v11 = o[nf][3] * inv1;
        size_t i0 = ((size_t)(b * Sc + row0)) * Dc + h * DKc + dk;
        size_t i1 = ((size_t)(b * Sc + row1)) * Dc + h * DKc + dk;
        *(uint32_t*)(g_Ch + i0) = packh2(v00, v01);
        *(uint32_t*)(g_Cl + i0) = packl2(v00, v01);
        *(uint32_t*)(g_Ch + i1) = packh2(v10, v11);
        *(uint32_t*)(g_Cl + i1) = packl2(v10, v11);
    }
}

// ---------------- launch ----------------
extern "C" void kernel_launch(void* const* d_in, const int* in_sizes, int n_in,
                              void* d_out, int out_size) {
    const float* query = (const float*)d_in[0];
    const float* key   = (const float*)d_in[1];
    const float* value = (const float*)d_in[2];
    const void*  pmask = d_in[3];
    const float* Wq = (const float*)d_in[4];
    const float* bq = (const float*)d_in[5];
    const float* Wk = (const float*)d_in[6];
    const float* bk = (const float*)d_in[7];
    const float* Wv = (const float*)d_in[8];
    const float* bv = (const float*)d_in[9];
    const float* Wo = (const float*)d_in[10];
    const float* bo = (const float*)d_in[11];
    float* out = (float*)d_out;

    detect_mask_k<<<1, 256>>>((const unsigned int*)pmask);
    expand_mask_k<<<(Bc * Sc + 255) / 256, 256>>>(pmask);

    SplitArgs sa;
    sa.src[0] = query; sa.src[1] = key; sa.src[2] = value;
    sa.src[3] = Wq; sa.src[4] = Wk; sa.src[5] = Wv; sa.src[6] = Wo;
    const int nAct4 = Mc * Dc / 4;
    dim3 gSplit((nAct4 + 255) / 256, 7);
    split_all_k<<<gSplit, 256>>>(sa);

    GemmBias gb;
    gb.b[0] = bq; gb.b[1] = bk; gb.b[2] = bv; gb.b[3] = bo;

    dim3 gQKV(Dc / 128, Mc / 128, 3);   // (8, 32, 3)
    gemm_k<<<gQKV, 256>>>(gb, -1, nullptr);

    vsuffix_k<<<Bc * Hc, DKc>>>();

    dim3 gAttn(Sc / 64, Bc * Hc);       // (32, 32)
    attn_k<<<gAttn, 128>>>();

    dim3 gOut(Dc / 128, Mc / 128);      // (8, 32)
    gemm_k<<<gOut, 256>>>(gb, 3, out);
}

// round 9
// speedup vs baseline: 1.3879x; 1.3116x over previous
#include <cuda_runtime.h>
#include <cuda_bf16.h>
#include <cstdint>

// Problem constants
#define Bc 2
#define Sc 2048
#define Dc 1024
#define Hc 16
#define DKc 64
#define Mc (Bc*Sc)   // 4096
#define NTILES 32    // Sc / 64

// ---------------- scratch (no allocations allowed) ----------------
__device__ __nv_bfloat16 g_Xh[3][Mc*Dc];
__device__ __nv_bfloat16 g_Xl[3][Mc*Dc];
__device__ __nv_bfloat16 g_Wh[4][Dc*Dc];
__device__ __nv_bfloat16 g_Wl[4][Dc*Dc];
__device__ __nv_bfloat16 g_Qh[Mc*Dc], g_Ql[Mc*Dc];
__device__ __nv_bfloat16 g_Kh[Mc*Dc], g_Kl[Mc*Dc];
__device__ __nv_bfloat16 g_Vh[Mc*Dc], g_Vl[Mc*Dc];
__device__ __nv_bfloat16 g_Ch[Mc*Dc], g_Cl[Mc*Dc];
__device__ float g_Vtile[Bc*Hc*NTILES*DKc];      // per-tile V sums
__device__ float g_Vsuf[Bc*Hc*(NTILES+1)*DKc];   // fp32 V suffix sums
__device__ float g_pm[Bc*Sc];
__device__ int   g_mask_mode;

// ---------------- helpers ----------------
__device__ __forceinline__ uint32_t smem_u32(const void* p) {
    return (uint32_t)__cvta_generic_to_shared(p);
}

#define MMA(c, a, b0, b1)                                                     \
    asm volatile(                                                             \
        "mma.sync.aligned.m16n8k16.row.col.f32.bf16.bf16.f32 "                \
        "{%0,%1,%2,%3},{%4,%5,%6,%7},{%8,%9},{%0,%1,%2,%3};\n"                \
        : "+f"((c)[0]), "+f"((c)[1]), "+f"((c)[2]), "+f"((c)[3])              \
        : "r"((a)[0]), "r"((a)[1]), "r"((a)[2]), "r"((a)[3]),                 \
          "r"(b0), "r"(b1));

#define LDMX4(r, addr)                                                        \
    asm volatile("ldmatrix.sync.aligned.m8n8.x4.shared.b16 {%0,%1,%2,%3}, [%4];" \
        : "=r"((r)[0]), "=r"((r)[1]), "=r"((r)[2]), "=r"((r)[3]) : "r"(addr));

#define LDMX4T(r, addr)                                                       \
    asm volatile("ldmatrix.sync.aligned.m8n8.x4.trans.shared.b16 {%0,%1,%2,%3}, [%4];" \
        : "=r"((r)[0]), "=r"((r)[1]), "=r"((r)[2]), "=r"((r)[3]) : "r"(addr));

#define CPA16(dst, src)                                                       \
    asm volatile("cp.async.cg.shared.global [%0], [%1], 16;\n"                \
        :: "r"(dst), "l"(src));
#define CPA_COMMIT() asm volatile("cp.async.commit_group;\n" ::: "memory")
#define CPA_WAIT0()  asm volatile("cp.async.wait_group 0;\n" ::: "memory")
#define CPA_WAIT1()  asm volatile("cp.async.wait_group 1;\n" ::: "memory")

__device__ __forceinline__ uint32_t packh2(float a, float b) {
    __nv_bfloat162 t;
    t.x = __float2bfloat16(a);
    t.y = __float2bfloat16(b);
    return *reinterpret_cast<uint32_t*>(&t);
}
__device__ __forceinline__ uint32_t packl2(float a, float b) {
    float ra = a - __bfloat162float(__float2bfloat16(a));
    float rb = b - __bfloat162float(__float2bfloat16(b));
    return packh2(ra, rb);
}

// ---------------- padding-mask dtype sniffing ----------------
__global__ void detect_mask_k(const unsigned int* __restrict__ mm) {
    __shared__ int okInt, okFloat;
    if (threadIdx.x == 0) { okInt = 1; okFloat = 1; }
    __syncthreads();
    for (int i = threadIdx.x; i < 1024; i += blockDim.x) {
        unsigned int v = mm[i];
        if (v > 1u) okInt = 0;
        if (v != 0u && v != 0x3F800000u) okFloat = 0;
    }
    __syncthreads();
    if (threadIdx.x == 0)
        g_mask_mode = okInt ? 1 : (okFloat ? 2 : 0);
}

__global__ void expand_mask_k(const void* __restrict__ mraw) {
    int i = blockIdx.x * blockDim.x + threadIdx.x;
    if (i >= Bc * Sc) return;
    int mode = g_mask_mode;
    float v;
    if (mode == 1)       v = (((const int*)mraw)[i] != 0) ? 1.f : 0.f;
    else if (mode == 2)  v = (((const float*)mraw)[i] != 0.f) ? 1.f : 0.f;
    else                 v = (((const unsigned char*)mraw)[i] != 0) ? 1.f : 0.f;
    g_pm[i] = v;
}

// ---------------- fp32 -> bf16 hi/lo split (all 7 tensors, one launch) ----------------
struct SplitArgs { const float* src[7]; };

__global__ void split_all_k(SplitArgs sa) {
    const int id = blockIdx.y;
    const int n4 = (id < 3) ? (Mc * Dc / 4) : (Dc * Dc / 4);
    int i = blockIdx.x * blockDim.x + threadIdx.x;
    if (i >= n4) return;
    __nv_bfloat16 *ph, *pl;
    if (id < 3) { ph = g_Xh[id]; pl = g_Xl[id]; }
    else        { ph = g_Wh[id - 3]; pl = g_Wl[id - 3]; }
    float4 v = ((const float4*)sa.src[id])[i];
    float a[4] = {v.x, v.y, v.z, v.w};
    __nv_bfloat162 h0, h1, l0, l1;
    h0.x = __float2bfloat16(a[0]); h0.y = __float2bfloat16(a[1]);
    h1.x = __float2bfloat16(a[2]); h1.y = __float2bfloat16(a[3]);
    l0.x = __float2bfloat16(a[0] - __bfloat162float(h0.x));
    l0.y = __float2bfloat16(a[1] - __bfloat162float(h0.y));
    l1.x = __float2bfloat16(a[2] - __bfloat162float(h1.x));
    l1.y = __float2bfloat16(a[3] - __bfloat162float(h1.y));
    ((__nv_bfloat162*)ph)[i * 2]     = h0;
    ((__nv_bfloat162*)ph)[i * 2 + 1] = h1;
    ((__nv_bfloat162*)pl)[i * 2]     = l0;
    ((__nv_bfloat162*)pl)[i * 2 + 1] = l1;
}

// ---------------- V tile sums + suffix scan (parallel) ----------------
__global__ void vtile_k() {
    const int bh = blockIdx.x, t = blockIdx.y, dk = threadIdx.x;
    const size_t base = (size_t)bh * Sc * DKc + (size_t)t * 64 * DKc + dk;
    float s = 0.f;
#pragma unroll 8
    for (int j = 0; j < 64; j++) {
        size_t idx = base + (size_t)j * DKc;
        s += __bfloat162float(g_Vh[idx]) + __bfloat162float(g_Vl[idx]);
    }
    g_Vtile[((size_t)bh * NTILES + t) * DKc + dk] = s;
}

__global__ void vscan_k() {
    const int bh = blockIdx.x, dk = threadIdx.x;
    float acc = 0.f;
    float* out = g_Vsuf + (size_t)bh * (NTILES + 1) * DKc + dk;
    out[NTILES * DKc] = 0.f;
    for (int t = NTILES - 1; t >= 0; t--) {
        acc += g_Vtile[((size_t)bh * NTILES + t) * DKc + dk];
        out[t * DKc] = acc;
    }
}

// ---------------- bf16 split-GEMM: 128x128x32, cp.async 2-stage, 2 CTA/SM ----------------
struct GemmBias { const float* b[4]; };

#define ASTR 40
#define BSTR 136
#define A_ELE (128*ASTR)                 // 5120 bf16
#define B_ELE (32*BSTR)                  // 4352 bf16
#define G_STAGE (2*A_ELE + 2*B_ELE)      // 18944 bf16 per stage
#define GEMM_SMEM (2*G_STAGE*2)          // 75776 bytes

__global__ __launch_bounds__(256, 2) void gemm_k(GemmBias gb, int mode_in, float* Cf) {
    extern __shared__ __align__(16) __nv_bfloat16 dsm[];
    const int mode = (mode_in < 0) ? (int)blockIdx.z : mode_in;
    const __nv_bfloat16 *Ah, *Al, *Bh, *Bl;
    __nv_bfloat16 *Oh = nullptr, *Ol = nullptr;
    if (mode < 3) {
        Ah = g_Xh[mode]; Al = g_Xl[mode];
        Bh = g_Wh[mode]; Bl = g_Wl[mode];
        Oh = (mode == 0) ? g_Qh : (mode == 1) ? g_Kh : g_Vh;
        Ol = (mode == 0) ? g_Ql : (mode == 1) ? g_Kl : g_Vl;
    } else {
        Ah = g_Ch; Al = g_Cl; Bh = g_Wh[3]; Bl = g_Wl[3];
    }
    const float* bias = gb.b[mode];

    const int tid = threadIdx.x;
    const int lane = tid & 31;
    const int wid = tid >> 5;
    const int wm = wid >> 2, wn = wid & 3;
    const int g = lane >> 2, tg = lane & 3;
    const int sub = lane >> 3, rr = lane & 7;
    const int mBase = blockIdx.y * 128, nBase = blockIdx.x * 128;

#define GEMM_ISSUE(kb, s)                                                      \
    {                                                                          \
        __nv_bfloat16* stg = dsm + (s) * G_STAGE;                              \
        _Pragma("unroll")                                                      \
        for (int i = 0; i < 2; i++) {                                          \
            int c = tid * 2 + i;                                               \
            int ar = c >> 2, ac = (c & 3) * 8;                                 \
            size_t aoff = (size_t)(mBase + ar) * Dc + (kb) * 32 + ac;          \
            CPA16(smem_u32(stg + ar * ASTR + ac), Ah + aoff);                  \
            CPA16(smem_u32(stg + A_ELE + ar * ASTR + ac), Al + aoff);          \
            int br = c >> 4, bc = (c & 15) * 8;                                \
            size_t boff = (size_t)((kb) * 32 + br) * Dc + nBase + bc;          \
            CPA16(smem_u32(stg + 2*A_ELE + br * BSTR + bc), Bh + boff);        \
            CPA16(smem_u32(stg + 2*A_ELE + B_ELE + br * BSTR + bc), Bl + boff);\
        }                                                                      \
        CPA_COMMIT();                                                          \
    }

    float acc[4][4][4];
#pragma unroll
    for (int i = 0; i < 4; i++)
#pragma unroll
        for (int j = 0; j < 4; j++)
#pragma unroll
            for (int k = 0; k < 4; k++) acc[i][j][k] = 0.f;

    GEMM_ISSUE(0, 0);

    const int KIT = Dc / 32;   // 32
    for (int kb = 0; kb < KIT; kb++) {
        const int st = kb & 1;
        if (kb + 1 < KIT) { GEMM_ISSUE(kb + 1, st ^ 1); CPA_WAIT1(); }
        else              { CPA_WAIT0(); }
        __syncthreads();

        const __nv_bfloat16* pAh = dsm + st * G_STAGE;
        const __nv_bfloat16* pAl = pAh + A_ELE;
        const __nv_bfloat16* pBh = pAh + 2 * A_ELE;
        const __nv_bfloat16* pBl = pBh + B_ELE;

#pragma unroll
        for (int ks = 0; ks < 2; ks++) {
            uint32_t fah[4][4], fal[4][4];
#pragma unroll
            for (int mf = 0; mf < 4; mf++) {
                int ar = wm * 64 + mf * 16 + (sub & 1) * 8 + rr;
                int ac = ks * 16 + (sub >> 1) * 8;
                LDMX4(fah[mf], smem_u32(pAh + ar * ASTR + ac));
                LDMX4(fal[mf], smem_u32(pAl + ar * ASTR + ac));
            }
            uint32_t fbh[2][4], fbl[2][4];
#pragma unroll
            for (int nb = 0; nb < 2; nb++) {
                int br = ks * 16 + (sub & 1) * 8 + rr;
                int bc = wn * 32 + nb * 16 + (sub >> 1) * 8;
                LDMX4T(fbh[nb], smem_u32(pBh + br * BSTR + bc));
                LDMX4T(fbl[nb], smem_u32(pBl + br * BSTR + bc));
            }
#pragma unroll
            for (int mf = 0; mf < 4; mf++)
#pragma unroll
                for (int nf = 0; nf < 4; nf++) {
                    uint32_t b0h = fbh[nf >> 1][(nf & 1) * 2];
                    uint32_t b1h = fbh[nf >> 1][(nf & 1) * 2 + 1];
                    uint32_t b0l = fbl[nf >> 1][(nf & 1) * 2];
                    uint32_t b1l = fbl[nf >> 1][(nf & 1) * 2 + 1];
                    MMA(acc[mf][nf], fah[mf], b0h, b1h);
                    MMA(acc[mf][nf], fah[mf], b0l, b1l);
                    MMA(acc[mf][nf], fal[mf], b0h, b1h);
                }
        }
        __syncthreads();
    }

    // epilogue
#pragma unroll
    for (int mf = 0; mf < 4; mf++) {
        int r0 = mBase + wm * 64 + mf * 16 + g;
        int r1 = r0 + 8;
#pragma unroll
        for (int nf = 0; nf < 4; nf++) {
            int n = nBase + wn * 32 + nf * 8 + tg * 2;
            float bv0 = bias[n], bv1 = bias[n + 1];
            float v00 = acc[mf][nf][0] + bv0, v01 = acc[mf][nf][1] + bv1;
            float v10 = acc[mf][nf][2] + bv0, v11 = acc[mf][nf][3] + bv1;
            if (mode == 3) {
                *(float2*)(Cf + (size_t)r0 * Dc + n) = make_float2(v00, v01);
                *(float2*)(Cf + (size_t)r1 * Dc + n) = make_float2(v10, v11);
            } else {
                int h = n >> 6, dk = n & 63;
#pragma unroll
                for (int p = 0; p < 2; p++) {
                    int r = p ? r1 : r0;
                    float a0 = p ? v10 : v00, a1 = p ? v11 : v01;
                    int b = r >> 11, s = r & 2047;
                    size_t idx = (((size_t)(b * Hc + h)) * Sc + s) * DKc + dk;
                    *(uint32_t*)(Oh + idx) = packh2(a0, a1);
                    *(uint32_t*)(Ol + idx) = packl2(a0, a1);
                }
            }
        }
    }
}

// ---------------- tensor-core flash attention, cp.async 2-stage + suffix skip ----------------
#define AT_A 4608                 // 64*72 bf16 per array
#define AT_STAGE (4*AT_A)         // 18432 bf16 per stage (Kh,Kl,Vh,Vl)
#define AT_PMS_OFF (2*AT_STAGE)   // bf16-element offset of pms area
#define ATTN_SMEM (2*AT_STAGE*2 + 2*64*4)   // 74240 bytes

__global__ __launch_bounds__(128) void attn_k() {
    extern __shared__ __align__(16) __nv_bfloat16 dsm[];
    float* pmsf = (float*)(dsm + AT_PMS_OFF);

    const int tid = threadIdx.x;
    const int lane = tid & 31;
    const int wid = tid >> 5;
    const int g = lane >> 2, tg = lane & 3;
    const int sub = lane >> 3, rr = lane & 7;
    const int bh = blockIdx.y, b = bh >> 4, h = bh & 15;
    const int qblk = (int)gridDim.x - 1 - (int)blockIdx.x;   // longest CTAs first
    const int q0 = qblk * 64;
    const int nT = qblk + 1;
    const size_t base = (size_t)bh * Sc * DKc;

#define ATTN_ISSUE(t, s)                                                       \
    {                                                                          \
        __nv_bfloat16* stg = dsm + (s) * AT_STAGE;                             \
        size_t tb = base + (size_t)((t) * 64) * DKc;                           \
        _Pragma("unroll")                                                      \
        for (int k2 = 0; k2 < 4; k2++) {                                       \
            int c = tid + k2 * 128;                                            \
            int row = c >> 3, col = (c & 7) * 8;                               \
            size_t off = tb + (size_t)row * DKc + col;                         \
            int d = row * 72 + col;                                            \
            CPA16(smem_u32(stg + d), g_Kh + off);                              \
            CPA16(smem_u32(stg + AT_A + d), g_Kl + off);                       \
            CPA16(smem_u32(stg + 2*AT_A + d), g_Vh + off);                     \
            CPA16(smem_u32(stg + 3*AT_A + d), g_Vl + off);                     \
        }                                                                      \
        if (tid < 16)                                                          \
            CPA16(smem_u32(pmsf + (s) * 64 + tid * 4),                         \
                  g_pm + b * Sc + (t) * 64 + tid * 4);                         \
        CPA_COMMIT();                                                          \
    }

    // start tile 0 streaming into stage 0; stage Q through stage-1 K buffers
    ATTN_ISSUE(0, 0);
    {
        __nv_bfloat16* qstg = dsm + AT_STAGE;
        for (int c = tid; c < 64 * 8; c += 128) {
            int row = c >> 3, col = (c & 7) * 8;
            size_t off = base + (size_t)(q0 + row) * DKc + col;
            *(uint4*)(qstg + row * 72 + col)        = *(const uint4*)(g_Qh + off);
            *(uint4*)(qstg + AT_A + row * 72 + col) = *(const uint4*)(g_Ql + off);
        }
    }
    __syncthreads();
    uint32_t qh[4][4], ql[4][4];
    {
        const __nv_bfloat16* qstg = dsm + AT_STAGE;
#pragma unroll
        for (int kb = 0; kb < 4; kb++) {
            int arow = wid * 16 + (sub & 1) * 8 + rr;
            int acol = kb * 16 + (sub >> 1) * 8;
            LDMX4(qh[kb], smem_u32(qstg + arow * 72 + acol));
            LDMX4(ql[kb], smem_u32(qstg + AT_A + arow * 72 + acol));
        }
    }
    __syncthreads();   // Q extraction done before tile-1 cp.async overwrites stage 1

    float o[8][4];
#pragma unroll
    for (int i = 0; i < 8; i++)
#pragma unroll
        for (int k = 0; k < 4; k++) o[i][k] = 0.f;
    float sum0 = 0.f, sum1 = 0.f;
    const int row0 = q0 + wid * 16 + g, row1 = row0 + 8;

    for (int t = 0; t < nT; t++) {
        const int st = t & 1;
        const int kv0 = t * 64;
        if (t + 1 < nT) { ATTN_ISSUE(t + 1, st ^ 1); CPA_WAIT1(); }
        else            { CPA_WAIT0(); }
        __syncthreads();

        const __nv_bfloat16* sKh = dsm + st * AT_STAGE;
        const __nv_bfloat16* sKl = sKh + AT_A;
        const __nv_bfloat16* sVh = sKh + 2 * AT_A;
        const __nv_bfloat16* sVl = sKh + 3 * AT_A;
        const float* pms = pmsf + st * 64;

        // S = Q K^T  (split, 3-term)
        float s[8][4];
#pragma unroll
        for (int i = 0; i < 8; i++)
#pragma unroll
            for (int k = 0; k < 4; k++) s[i][k] = 0.f;
#pragma unroll
        for (int jj = 0; jj < 4; jj++) {
#pragma unroll
            for (int kb = 0; kb < 4; kb++) {
                uint32_t bKh[4], bKl[4];
                int krow = jj * 16 + (sub >> 1) * 8 + rr;
                int kcol = kb * 16 + (sub & 1) * 8;
                LDMX4(bKh, smem_u32(sKh + krow * 72 + kcol));
                LDMX4(bKl, smem_u32(sKl + krow * 72 + kcol));
                MMA(s[2 * jj],     qh[kb], bKh[0], bKh[1]);
                MMA(s[2 * jj],     qh[kb], bKl[0], bKl[1]);
                MMA(s[2 * jj],     ql[kb], bKh[0], bKh[1]);
                MMA(s[2 * jj + 1], qh[kb], bKh[2], bKh[3]);
                MMA(s[2 * jj + 1], qh[kb], bKl[2], bKl[3]);
                MMA(s[2 * jj + 1], ql[kb], bKh[2], bKh[3]);
            }
        }

        // mask + exp, re-pack as P A-fragments
        uint32_t ph[4][4], pl[4][4];
#pragma unroll
        for (int j = 0; j < 8; j++) {
            int cg = kv0 + j * 8 + tg * 2;
            float2 mv = *(float2*)&pms[j * 8 + tg * 2];
            float sc0 = (cg     > row0 || mv.x != 0.f) ? 1e-10f : s[j][0] * 0.125f;
            float sc1 = (cg + 1 > row0 || mv.y != 0.f) ? 1e-10f : s[j][1] * 0.125f;
            float sc2 = (cg     > row1 || mv.x != 0.f) ? 1e-10f : s[j][2] * 0.125f;
            float sc3 = (cg + 1 > row1 || mv.y != 0.f) ? 1e-10f : s[j][3] * 0.125f;
            float e0 = __expf(sc0), e1 = __expf(sc1);
            float e2 = __expf(sc2), e3 = __expf(sc3);
            sum0 += e0 + e1;
            sum1 += e2 + e3;
            int tt = j >> 1;
            if ((j & 1) == 0) {
                ph[tt][0] = packh2(e0, e1); ph[tt][1] = packh2(e2, e3);
                pl[tt][0] = packl2(e0, e1); pl[tt][1] = packl2(e2, e3);
            } else {
                ph[tt][2] = packh2(e0, e1); ph[tt][3] = packh2(e2, e3);
                pl[tt][2] = packl2(e0, e1); pl[tt][3] = packl2(e2, e3);
            }
        }

        // O += P V  (split, 3-term)
#pragma unroll
        for (int dd = 0; dd < 4; dd++) {
#pragma unroll
            for (int tt = 0; tt < 4; tt++) {
                uint32_t vh_[4], vl_[4];
                int vrow = tt * 16 + (sub & 1) * 8 + rr;
                int vcol = dd * 16 + (sub >> 1) * 8;
                LDMX4T(vh_, smem_u32(sVh + vrow * 72 + vcol));
                LDMX4T(vl_, smem_u32(sVl + vrow * 72 + vcol));
                MMA(o[2 * dd],     ph[tt], vh_[0], vh_[1]);
                MMA(o[2 * dd],     ph[tt], vl_[0], vl_[1]);
                MMA(o[2 * dd],     pl[tt], vh_[0], vh_[1]);
                MMA(o[2 * dd + 1], ph[tt], vh_[2], vh_[3]);
                MMA(o[2 * dd + 1], ph[tt], vl_[2], vl_[3]);
                MMA(o[2 * dd + 1], pl[tt], vh_[2], vh_[3]);
            }
        }
        __syncthreads();
    }

    // future keys: per-lane-owned o elements get the fp32 suffix sum
    {
        const float* suf = g_Vsuf + ((size_t)bh * (NTILES + 1) + nT) * DKc;
#pragma unroll
        for (int nf = 0; nf < 8; nf++) {
            int col = nf * 8 + tg * 2;
            float vA = suf[col], vB = suf[col + 1];
            o[nf][0] += vA; o[nf][1] += vB;
            o[nf][2] += vA; o[nf][3] += vB;
        }
    }

    // rowsum reduce over the 4 lanes sharing a row, THEN add future-key count once
    sum0 += __shfl_xor_sync(0xFFFFFFFFu, sum0, 1);
    sum0 += __shfl_xor_sync(0xFFFFFFFFu, sum0, 2);
    sum1 += __shfl_xor_sync(0xFFFFFFFFu, sum1, 1);
    sum1 += __shfl_xor_sync(0xFFFFFFFFu, sum1, 2);
    const float cnt = (float)(Sc - nT * 64);
    sum0 += cnt;
    sum1 += cnt;
    float inv0 = 1.f / sum0, inv1 = 1.f / sum1;

#pragma unroll
    for (int nf = 0; nf < 8; nf++) {
        int dk = nf * 8 + tg * 2;
        float v00 = o[nf][0] * inv0, v01 = o[nf][1] * inv0;
        float v10 = o[nf][2] * inv1, v11 = o[nf][3] * inv1;
        size_t i0 = ((size_t)(b * Sc + row0)) * Dc + h * DKc + dk;
        size_t i1 = ((size_t)(b * Sc + row1)) * Dc + h * DKc + dk;
        *(uint32_t*)(g_Ch + i0) = packh2(v00, v01);
        *(uint32_t*)(g_Cl + i0) = packl2(v00, v01);
        *(uint32_t*)(g_Ch + i1) = packh2(v10, v11);
        *(uint32_t*)(g_Cl + i1) = packl2(v10, v11);
    }
}

// ---------------- launch ----------------
extern "C" void kernel_launch(void* const* d_in, const int* in_sizes, int n_in,
                              void* d_out, int out_size) {
    const float* query = (const float*)d_in[0];
    const float* key   = (const float*)d_in[1];
    const float* value = (const float*)d_in[2];
    const void*  pmask = d_in[3];
    const float* Wq = (const float*)d_in[4];
    const float* bq = (const float*)d_in[5];
    const float* Wk = (const float*)d_in[6];
    const float* bk = (const float*)d_in[7];
    const float* Wv = (const float*)d_in[8];
    const float* bv = (const float*)d_in[9];
    const float* Wo = (const float*)d_in[10];
    const float* bo = (const float*)d_in[11];
    float* out = (float*)d_out;

    cudaFuncSetAttribute(gemm_k, cudaFuncAttributeMaxDynamicSharedMemorySize, GEMM_SMEM);
    cudaFuncSetAttribute(attn_k, cudaFuncAttributeMaxDynamicSharedMemorySize, ATTN_SMEM);

    detect_mask_k<<<1, 256>>>((const unsigned int*)pmask);
    expand_mask_k<<<(Bc * Sc + 255) / 256, 256>>>(pmask);

    SplitArgs sa;
    sa.src[0] = query; sa.src[1] = key; sa.src[2] = value;
    sa.src[3] = Wq; sa.src[4] = Wk; sa.src[5] = Wv; sa.src[6] = Wo;
    const int nAct4 = Mc * Dc / 4;
    dim3 gSplit((nAct4 + 255) / 256, 7);
    split_all_k<<<gSplit, 256>>>(sa);

    GemmBias gb;
    gb.b[0] = bq; gb.b[1] = bk; gb.b[2] = bv; gb.b[3] = bo;

    dim3 gQKV(Dc / 128, Mc / 128, 3);   // (8, 32, 3)
    gemm_k<<<gQKV, 256, GEMM_SMEM>>>(gb, -1, nullptr);

    dim3 gVt(Bc * Hc, NTILES);
    vtile_k<<<gVt, DKc>>>();
    vscan_k<<<Bc * Hc, DKc>>>();

    dim3 gAttn(Sc / 64, Bc * Hc);       // (32, 32)
    attn_k<<<gAttn, 128, ATTN_SMEM>>>();

    dim3 gOut(Dc / 128, Mc / 128);      // (8, 32)
    gemm_k<<<gOut, 256, GEMM_SMEM>>>(gb, 3, out);
}

// round 11
// speedup vs baseline: 1.4566x; 1.0495x over previous
#include <cuda_runtime.h>
#include <cuda_bf16.h>
#include <cstdint>

// Problem constants
#define Bc 2
#define Sc 2048
#define Dc 1024
#define Hc 16
#define DKc 64
#define Mc (Bc*Sc)   // 4096
#define NTILES 32    // Sc / 64

// ---------------- scratch (no allocations allowed) ----------------
__device__ __nv_bfloat16 g_Xh[3][Mc*Dc];
__device__ __nv_bfloat16 g_Xl[3][Mc*Dc];
__device__ __nv_bfloat16 g_Wh[4][Dc*Dc];   // [k][n] as given
__device__ __nv_bfloat16 g_Wl[4][Dc*Dc];
__device__ __nv_bfloat16 g_Qh[Mc*Dc], g_Ql[Mc*Dc];
__device__ __nv_bfloat16 g_Kh[Mc*Dc], g_Kl[Mc*Dc];
__device__ __nv_bfloat16 g_Vh[Mc*Dc], g_Vl[Mc*Dc];
__device__ __nv_bfloat16 g_Ch[Mc*Dc], g_Cl[Mc*Dc];
__device__ float g_Vtile[Bc*Hc*NTILES*DKc];
__device__ float g_Vsuf[Bc*Hc*(NTILES+1)*DKc];
__device__ float g_pm[Bc*Sc];
__device__ int   g_mask_mode;

// ---------------- helpers ----------------
__device__ __forceinline__ uint32_t smem_u32(const void* p) {
    return (uint32_t)__cvta_generic_to_shared(p);
}

#define MMA(c, a, b0, b1)                                                     \
    asm volatile(                                                             \
        "mma.sync.aligned.m16n8k16.row.col.f32.bf16.bf16.f32 "                \
        "{%0,%1,%2,%3},{%4,%5,%6,%7},{%8,%9},{%0,%1,%2,%3};\n"                \
        : "+f"((c)[0]), "+f"((c)[1]), "+f"((c)[2]), "+f"((c)[3])              \
        : "r"((a)[0]), "r"((a)[1]), "r"((a)[2]), "r"((a)[3]),                 \
          "r"(b0), "r"(b1));

#define LDMX4(r, addr)                                                        \
    asm volatile("ldmatrix.sync.aligned.m8n8.x4.shared.b16 {%0,%1,%2,%3}, [%4];" \
        : "=r"((r)[0]), "=r"((r)[1]), "=r"((r)[2]), "=r"((r)[3]) : "r"(addr));

#define LDMX4T(r, addr)                                                       \
    asm volatile("ldmatrix.sync.aligned.m8n8.x4.trans.shared.b16 {%0,%1,%2,%3}, [%4];" \
        : "=r"((r)[0]), "=r"((r)[1]), "=r"((r)[2]), "=r"((r)[3]) : "r"(addr));

#define CPA16(dst, src)                                                       \
    asm volatile("cp.async.cg.shared.global [%0], [%1], 16;\n"                \
        :: "r"(dst), "l"(src));
#define CPA_COMMIT() asm volatile("cp.async.commit_group;\n" ::: "memory")
#define CPA_WAIT0()  asm volatile("cp.async.wait_group 0;\n" ::: "memory")
#define CPA_WAIT1()  asm volatile("cp.async.wait_group 1;\n" ::: "memory")

__device__ __forceinline__ uint32_t packh2(float a, float b) {
    __nv_bfloat162 t;
    t.x = __float2bfloat16(a);
    t.y = __float2bfloat16(b);
    return *reinterpret_cast<uint32_t*>(&t);
}
__device__ __forceinline__ uint32_t packl2(float a, float b) {
    float ra = a - __bfloat162float(__float2bfloat16(a));
    float rb = b - __bfloat162float(__float2bfloat16(b));
    return packh2(ra, rb);
}

// ---------------- padding-mask dtype sniffing ----------------
__global__ void detect_mask_k(const unsigned int* __restrict__ mm) {
    __shared__ int okInt, okFloat;
    if (threadIdx.x == 0) { okInt = 1; okFloat = 1; }
    __syncthreads();
    for (int i = threadIdx.x; i < 1024; i += blockDim.x) {
        unsigned int v = mm[i];
        if (v > 1u) okInt = 0;
        if (v != 0u && v != 0x3F800000u) okFloat = 0;
    }
    __syncthreads();
    if (threadIdx.x == 0)
        g_mask_mode = okInt ? 1 : (okFloat ? 2 : 0);
}

__global__ void expand_mask_k(const void* __restrict__ mraw) {
    int i = blockIdx.x * blockDim.x + threadIdx.x;
    if (i >= Bc * Sc) return;
    int mode = g_mask_mode;
    float v;
    if (mode == 1)       v = (((const int*)mraw)[i] != 0) ? 1.f : 0.f;
    else if (mode == 2)  v = (((const float*)mraw)[i] != 0.f) ? 1.f : 0.f;
    else                 v = (((const unsigned char*)mraw)[i] != 0) ? 1.f : 0.f;
    g_pm[i] = v;
}

// ---------------- fp32 -> bf16 hi/lo split (all 7 tensors, one launch) ----------------
struct SplitArgs { const float* src[7]; };

__global__ void split_all_k(SplitArgs sa) {
    const int id = blockIdx.y;
    const int n4 = (id < 3) ? (Mc * Dc / 4) : (Dc * Dc / 4);
    int i = blockIdx.x * blockDim.x + threadIdx.x;
    if (i >= n4) return;
    __nv_bfloat16 *ph, *pl;
    if (id < 3) { ph = g_Xh[id]; pl = g_Xl[id]; }
    else        { ph = g_Wh[id - 3]; pl = g_Wl[id - 3]; }
    float4 v = ((const float4*)sa.src[id])[i];
    float a[4] = {v.x, v.y, v.z, v.w};
    __nv_bfloat162 h0, h1, l0, l1;
    h0.x = __float2bfloat16(a[0]); h0.y = __float2bfloat16(a[1]);
    h1.x = __float2bfloat16(a[2]); h1.y = __float2bfloat16(a[3]);
    l0.x = __float2bfloat16(a[0] - __bfloat162float(h0.x));
    l0.y = __float2bfloat16(a[1] - __bfloat162float(h0.y));
    l1.x = __float2bfloat16(a[2] - __bfloat162float(h1.x));
    l1.y = __float2bfloat16(a[3] - __bfloat162float(h1.y));
    ((__nv_bfloat162*)ph)[i * 2]     = h0;
    ((__nv_bfloat162*)ph)[i * 2 + 1] = h1;
    ((__nv_bfloat162*)pl)[i * 2]     = l0;
    ((__nv_bfloat162*)pl)[i * 2 + 1] = l1;
}

// ---------------- V tile sums + suffix scan (parallel) ----------------
__global__ void vtile_k() {
    const int bh = blockIdx.x, t = blockIdx.y, dk = threadIdx.x;
    const size_t base = (size_t)bh * Sc * DKc + (size_t)t * 64 * DKc + dk;
    float s = 0.f;
#pragma unroll 8
    for (int j = 0; j < 64; j++) {
        size_t idx = base + (size_t)j * DKc;
        s += __bfloat162float(g_Vh[idx]) + __bfloat162float(g_Vl[idx]);
    }
    g_Vtile[((size_t)bh * NTILES + t) * DKc + dk] = s;
}

__global__ void vscan_k() {
    const int bh = blockIdx.x, dk = threadIdx.x;
    float acc = 0.f;
    float* out = g_Vsuf + (size_t)bh * (NTILES + 1) * DKc + dk;
    out[NTILES * DKc] = 0.f;
    for (int t = NTILES - 1; t >= 0; t--) {
        acc += g_Vtile[((size_t)bh * NTILES + t) * DKc + dk];
        out[t * DKc] = acc;
    }
}

// ---------------- bf16 split-GEMM: 128x128x32, 4 warps (2x2), 64x64 warp tile ----------
// cp.async 2-stage double buffer, 2 CTAs/SM. 6 MMA per ldmatrix (was 4).
struct GemmBias { const float* b[4]; };

#define ASTR 40
#define BSTR 136
#define A_ELE (128*ASTR)                 // 5120 bf16
#define B_ELE (32*BSTR)                  // 4352 bf16
#define G_STAGE (2*A_ELE + 2*B_ELE)      // 18944 bf16 per stage
#define GEMM_SMEM (2*G_STAGE*2)          // 75776 bytes

__global__ __launch_bounds__(128, 2) void gemm_k(GemmBias gb, int mode_in, float* Cf) {
    extern __shared__ __align__(16) __nv_bfloat16 dsm[];
    const int mode = (mode_in < 0) ? (int)blockIdx.z : mode_in;
    const __nv_bfloat16 *Ah, *Al, *Bh, *Bl;
    __nv_bfloat16 *Oh = nullptr, *Ol = nullptr;
    if (mode < 3) {
        Ah = g_Xh[mode]; Al = g_Xl[mode];
        Bh = g_Wh[mode]; Bl = g_Wl[mode];
        Oh = (mode == 0) ? g_Qh : (mode == 1) ? g_Kh : g_Vh;
        Ol = (mode == 0) ? g_Ql : (mode == 1) ? g_Kl : g_Vl;
    } else {
        Ah = g_Ch; Al = g_Cl; Bh = g_Wh[3]; Bl = g_Wl[3];
    }
    const float* bias = gb.b[mode];

    const int tid = threadIdx.x;
    const int lane = tid & 31;
    const int wid = tid >> 5;              // 0..3
    const int wm = wid >> 1, wn = wid & 1; // 2 x 2 warp grid, 64x64 tiles
    const int g = lane >> 2, tg = lane & 3;
    const int sub = lane >> 3, rr = lane & 7;
    const int mBase = blockIdx.y * 128, nBase = blockIdx.x * 128;

#define GEMM_ISSUE(kb, s)                                                      \
    {                                                                          \
        __nv_bfloat16* stg = dsm + (s) * G_STAGE;                              \
        _Pragma("unroll")                                                      \
        for (int i = 0; i < 4; i++) {                                          \
            int c = tid + 128 * i;                                             \
            int ar = c >> 2, ac = (c & 3) * 8;                                 \
            size_t aoff = (size_t)(mBase + ar) * Dc + (kb) * 32 + ac;          \
            CPA16(smem_u32(stg + ar * ASTR + ac), Ah + aoff);                  \
            CPA16(smem_u32(stg + A_ELE + ar * ASTR + ac), Al + aoff);          \
            int br = c >> 4, bc = (c & 15) * 8;                                \
            size_t boff = (size_t)((kb) * 32 + br) * Dc + nBase + bc;          \
            CPA16(smem_u32(stg + 2*A_ELE + br * BSTR + bc), Bh + boff);        \
            CPA16(smem_u32(stg + 2*A_ELE + B_ELE + br * BSTR + bc), Bl + boff);\
        }                                                                      \
        CPA_COMMIT();                                                          \
    }

    float acc[4][8][4];
#pragma unroll
    for (int i = 0; i < 4; i++)
#pragma unroll
        for (int j = 0; j < 8; j++)
#pragma unroll
            for (int k = 0; k < 4; k++) acc[i][j][k] = 0.f;

    GEMM_ISSUE(0, 0);

    const int KIT = Dc / 32;   // 32
    for (int kb = 0; kb < KIT; kb++) {
        const int st = kb & 1;
        if (kb + 1 < KIT) { GEMM_ISSUE(kb + 1, st ^ 1); CPA_WAIT1(); }
        else              { CPA_WAIT0(); }
        __syncthreads();

        const __nv_bfloat16* pAh = dsm + st * G_STAGE;
        const __nv_bfloat16* pAl = pAh + A_ELE;
        const __nv_bfloat16* pBh = pAh + 2 * A_ELE;
        const __nv_bfloat16* pBl = pBh + B_ELE;

#pragma unroll
        for (int ks = 0; ks < 2; ks++) {
            uint32_t fah[4][4], fal[4][4];
#pragma unroll
            for (int mf = 0; mf < 4; mf++) {
                int ar = wm * 64 + mf * 16 + (sub & 1) * 8 + rr;
                int ac = ks * 16 + (sub >> 1) * 8;
                LDMX4(fah[mf], smem_u32(pAh + ar * ASTR + ac));
                LDMX4(fal[mf], smem_u32(pAl + ar * ASTR + ac));
            }
#pragma unroll
            for (int nb = 0; nb < 4; nb++) {
                uint32_t bh_[4], bl_[4];
                int br = ks * 16 + (sub & 1) * 8 + rr;
                int bc = wn * 64 + nb * 16 + (sub >> 1) * 8;
                LDMX4T(bh_, smem_u32(pBh + br * BSTR + bc));
                LDMX4T(bl_, smem_u32(pBl + br * BSTR + bc));
#pragma unroll
                for (int mf = 0; mf < 4; mf++) {
                    MMA(acc[mf][2*nb],     fah[mf], bh_[0], bh_[1]);
                    MMA(acc[mf][2*nb],     fah[mf], bl_[0], bl_[1]);
                    MMA(acc[mf][2*nb],     fal[mf], bh_[0], bh_[1]);
                    MMA(acc[mf][2*nb + 1], fah[mf], bh_[2], bh_[3]);
                    MMA(acc[mf][2*nb + 1], fah[mf], bl_[2], bl_[3]);
                    MMA(acc[mf][2*nb + 1], fal[mf], bh_[2], bh_[3]);
                }
            }
        }
        __syncthreads();
    }

    // epilogue
#pragma unroll
    for (int mf = 0; mf < 4; mf++) {
        int r0 = mBase + wm * 64 + mf * 16 + g;
        int r1 = r0 + 8;
#pragma unroll
        for (int nf = 0; nf < 8; nf++) {
            int n = nBase + wn * 64 + nf * 8 + tg * 2;
            float bv0 = bias[n], bv1 = bias[n + 1];
            float v00 = acc[mf][nf][0] + bv0, v01 = acc[mf][nf][1] + bv1;
            float v10 = acc[mf][nf][2] + bv0, v11 = acc[mf][nf][3] + bv1;
            if (mode == 3) {
                *(float2*)(Cf + (size_t)r0 * Dc + n) = make_float2(v00, v01);
                *(float2*)(Cf + (size_t)r1 * Dc + n) = make_float2(v10, v11);
            } else {
                int h = n >> 6, dk = n & 63;
#pragma unroll
                for (int p = 0; p < 2; p++) {
                    int r = p ? r1 : r0;
                    float a0 = p ? v10 : v00, a1 = p ? v11 : v01;
                    int b = r >> 11, s = r & 2047;
                    size_t idx = (((size_t)(b * Hc + h)) * Sc + s) * DKc + dk;
                    *(uint32_t*)(Oh + idx) = packh2(a0, a1);
                    *(uint32_t*)(Ol + idx) = packl2(a0, a1);
                }
            }
        }
    }
}

// ---------------- tensor-core flash attention, cp.async 2-stage + suffix skip ----------------
#define AT_A 4608                 // 64*72 bf16 per array
#define AT_STAGE (4*AT_A)         // per stage (Kh,Kl,Vh,Vl)
#define AT_PMS_OFF (2*AT_STAGE)
#define ATTN_SMEM (2*AT_STAGE*2 + 2*64*4)   // 74240 bytes

__global__ __launch_bounds__(128) void attn_k() {
    extern __shared__ __align__(16) __nv_bfloat16 adsm[];
    float* pmsf = (float*)(adsm + AT_PMS_OFF);

    const int tid = threadIdx.x;
    const int lane = tid & 31;
    const int wid = tid >> 5;
    const int g = lane >> 2, tg = lane & 3;
    const int sub = lane >> 3, rr = lane & 7;
    const int bh = blockIdx.y, b = bh >> 4, h = bh & 15;
    const int qblk = (int)gridDim.x - 1 - (int)blockIdx.x;   // longest CTAs first
    const int q0 = qblk * 64;
    const int nT = qblk + 1;
    const size_t base = (size_t)bh * Sc * DKc;

#define ATTN_ISSUE(t, s)                                                       \
    {                                                                          \
        __nv_bfloat16* stg = adsm + (s) * AT_STAGE;                            \
        size_t tb = base + (size_t)((t) * 64) * DKc;                           \
        _Pragma("unroll")                                                      \
        for (int k2 = 0; k2 < 4; k2++) {                                       \
            int c = tid + k2 * 128;                                            \
            int row = c >> 3, col = (c & 7) * 8;                               \
            size_t off = tb + (size_t)row * DKc + col;                         \
            int d = row * 72 + col;                                            \
            CPA16(smem_u32(stg + d), g_Kh + off);                              \
            CPA16(smem_u32(stg + AT_A + d), g_Kl + off);                       \
            CPA16(smem_u32(stg + 2*AT_A + d), g_Vh + off);                     \
            CPA16(smem_u32(stg + 3*AT_A + d), g_Vl + off);                     \
        }                                                                      \
        if (tid < 16)                                                          \
            CPA16(smem_u32(pmsf + (s) * 64 + tid * 4),                         \
                  g_pm + b * Sc + (t) * 64 + tid * 4);                         \
        CPA_COMMIT();                                                          \
    }

    ATTN_ISSUE(0, 0);
    {
        __nv_bfloat16* qstg = adsm + AT_STAGE;
        for (int c = tid; c < 64 * 8; c += 128) {
            int row = c >> 3, col = (c & 7) * 8;
            size_t off = base + (size_t)(q0 + row) * DKc + col;
            *(uint4*)(qstg + row * 72 + col)        = *(const uint4*)(g_Qh + off);
            *(uint4*)(qstg + AT_A + row * 72 + col) = *(const uint4*)(g_Ql + off);
        }
    }
    __syncthreads();
    uint32_t qh[4][4], ql[4][4];
    {
        const __nv_bfloat16* qstg = adsm + AT_STAGE;
#pragma unroll
        for (int kb = 0; kb < 4; kb++) {
            int arow = wid * 16 + (sub & 1) * 8 + rr;
            int acol = kb * 16 + (sub >> 1) * 8;
            LDMX4(qh[kb], smem_u32(qstg + arow * 72 + acol));
            LDMX4(ql[kb], smem_u32(qstg + AT_A + arow * 72 + acol));
        }
    }
    __syncthreads();   // Q extraction done before tile-1 cp.async overwrites stage 1

    float o[8][4];
#pragma unroll
    for (int i = 0; i < 8; i++)
#pragma unroll
        for (int k = 0; k < 4; k++) o[i][k] = 0.f;
    float sum0 = 0.f, sum1 = 0.f;
    const int row0 = q0 + wid * 16 + g, row1 = row0 + 8;

    for (int t = 0; t < nT; t++) {
        const int st = t & 1;
        const int kv0 = t * 64;
        if (t + 1 < nT) { ATTN_ISSUE(t + 1, st ^ 1); CPA_WAIT1(); }
        else            { CPA_WAIT0(); }
        __syncthreads();

        const __nv_bfloat16* sKh = adsm + st * AT_STAGE;
        const __nv_bfloat16* sKl = sKh + AT_A;
        const __nv_bfloat16* sVh = sKh + 2 * AT_A;
        const __nv_bfloat16* sVl = sKh + 3 * AT_A;
        const float* pms = pmsf + st * 64;

        float s[8][4];
#pragma unroll
        for (int i = 0; i < 8; i++)
#pragma unroll
            for (int k = 0; k < 4; k++) s[i][k] = 0.f;
#pragma unroll
        for (int jj = 0; jj < 4; jj++) {
#pragma unroll
            for (int kb = 0; kb < 4; kb++) {
                uint32_t bKh[4], bKl[4];
                int krow = jj * 16 + (sub >> 1) * 8 + rr;
                int kcol = kb * 16 + (sub & 1) * 8;
                LDMX4(bKh, smem_u32(sKh + krow * 72 + kcol));
                LDMX4(bKl, smem_u32(sKl + krow * 72 + kcol));
                MMA(s[2 * jj],     qh[kb], bKh[0], bKh[1]);
                MMA(s[2 * jj],     qh[kb], bKl[0], bKl[1]);
                MMA(s[2 * jj],     ql[kb], bKh[0], bKh[1]);
                MMA(s[2 * jj + 1], qh[kb], bKh[2], bKh[3]);
                MMA(s[2 * jj + 1], qh[kb], bKl[2], bKl[3]);
                MMA(s[2 * jj + 1], ql[kb], bKh[2], bKh[3]);
            }
        }

        uint32_t ph[4][4], pl[4][4];
#pragma unroll
        for (int j = 0; j < 8; j++) {
            int cg = kv0 + j * 8 + tg * 2;
            float2 mv = *(float2*)&pms[j * 8 + tg * 2];
            float sc0 = (cg     > row0 || mv.x != 0.f) ? 1e-10f : s[j][0] * 0.125f;
            float sc1 = (cg + 1 > row0 || mv.y != 0.f) ? 1e-10f : s[j][1] * 0.125f;
            float sc2 = (cg     > row1 || mv.x != 0.f) ? 1e-10f : s[j][2] * 0.125f;
            float sc3 = (cg + 1 > row1 || mv.y != 0.f) ? 1e-10f : s[j][3] * 0.125f;
            float e0 = __expf(sc0), e1 = __expf(sc1);
            float e2 = __expf(sc2), e3 = __expf(sc3);
            sum0 += e0 + e1;
            sum1 += e2 + e3;
            int tt = j >> 1;
            if ((j & 1) == 0) {
                ph[tt][0] = packh2(e0, e1); ph[tt][1] = packh2(e2, e3);
                pl[tt][0] = packl2(e0, e1); pl[tt][1] = packl2(e2, e3);
            } else {
                ph[tt][2] = packh2(e0, e1); ph[tt][3] = packh2(e2, e3);
                pl[tt][2] = packl2(e0, e1); pl[tt][3] = packl2(e2, e3);
            }
        }

#pragma unroll
        for (int dd = 0; dd < 4; dd++) {
#pragma unroll
            for (int tt = 0; tt < 4; tt++) {
                uint32_t vh_[4], vl_[4];
                int vrow = tt * 16 + (sub & 1) * 8 + rr;
                int vcol = dd * 16 + (sub >> 1) * 8;
                LDMX4T(vh_, smem_u32(sVh + vrow * 72 + vcol));
                LDMX4T(vl_, smem_u32(sVl + vrow * 72 + vcol));
                MMA(o[2 * dd],     ph[tt], vh_[0], vh_[1]);
                MMA(o[2 * dd],     ph[tt], vl_[0], vl_[1]);
                MMA(o[2 * dd],     pl[tt], vh_[0], vh_[1]);
                MMA(o[2 * dd + 1], ph[tt], vh_[2], vh_[3]);
                MMA(o[2 * dd + 1], ph[tt], vl_[2], vl_[3]);
                MMA(o[2 * dd + 1], pl[tt], vh_[2], vh_[3]);
            }
        }
        __syncthreads();
    }

    {
        const float* suf = g_Vsuf + ((size_t)bh * (NTILES + 1) + nT) * DKc;
#pragma unroll
        for (int nf = 0; nf < 8; nf++) {
            int col = nf * 8 + tg * 2;
            float vA = suf[col], vB = suf[col + 1];
            o[nf][0] += vA; o[nf][1] += vB;
            o[nf][2] += vA; o[nf][3] += vB;
        }
    }

    sum0 += __shfl_xor_sync(0xFFFFFFFFu, sum0, 1);
    sum0 += __shfl_xor_sync(0xFFFFFFFFu, sum0, 2);
    sum1 += __shfl_xor_sync(0xFFFFFFFFu, sum1, 1);
    sum1 += __shfl_xor_sync(0xFFFFFFFFu, sum1, 2);
    const float cnt = (float)(Sc - nT * 64);
    sum0 += cnt;
    sum1 += cnt;
    float inv0 = 1.f / sum0, inv1 = 1.f / sum1;

#pragma unroll
    for (int nf = 0; nf < 8; nf++) {
        int dk = nf * 8 + tg * 2;
        float v00 = o[nf][0] * inv0, v01 = o[nf][1] * inv0;
        float v10 = o[nf][2] * inv1, v11 = o[nf][3] * inv1;
        size_t i0 = ((size_t)(b * Sc + row0)) * Dc + h * DKc + dk;
        size_t i1 = ((size_t)(b * Sc + row1)) * Dc + h * DKc + dk;
        *(uint32_t*)(g_Ch + i0) = packh2(v00, v01);
        *(uint32_t*)(g_Cl + i0) = packl2(v00, v01);
        *(uint32_t*)(g_Ch + i1) = packh2(v10, v11);
        *(uint32_t*)(g_Cl + i1) = packl2(v10, v11);
    }
}

// ---------------- launch ----------------
extern "C" void kernel_launch(void* const* d_in, const int* in_sizes, int n_in,
                              void* d_out, int out_size) {
    const float* query = (const float*)d_in[0];
    const float* key   = (const float*)d_in[1];
    const float* value = (const float*)d_in[2];
    const void*  pmask = d_in[3];
    const float* Wq = (const float*)d_in[4];
    const float* bq = (const float*)d_in[5];
    const float* Wk = (const float*)d_in[6];
    const float* bk = (const float*)d_in[7];
    const float* Wv = (const float*)d_in[8];
    const float* bv = (const float*)d_in[9];
    const float* Wo = (const float*)d_in[10];
    const float* bo = (const float*)d_in[11];
    float* out = (float*)d_out;

    cudaFuncSetAttribute(gemm_k, cudaFuncAttributeMaxDynamicSharedMemorySize, GEMM_SMEM);
    cudaFuncSetAttribute(attn_k, cudaFuncAttributeMaxDynamicSharedMemorySize, ATTN_SMEM);

    detect_mask_k<<<1, 256>>>((const unsigned int*)pmask);
    expand_mask_k<<<(Bc * Sc + 255) / 256, 256>>>(pmask);

    SplitArgs sa;
    sa.src[0] = query; sa.src[1] = key; sa.src[2] = value;
    sa.src[3] = Wq; sa.src[4] = Wk; sa.src[5] = Wv; sa.src[6] = Wo;
    const int nAct4 = Mc * Dc / 4;
    dim3 gSplit((nAct4 + 255) / 256, 7);
    split_all_k<<<gSplit, 256>>>(sa);

    GemmBias gb;
    gb.b[0] = bq; gb.b[1] = bk; gb.b[2] = bv; gb.b[3] = bo;

    dim3 gQKV(Dc / 128, Mc / 128, 3);   // (8, 32, 3)
    gemm_k<<<gQKV, 128, GEMM_SMEM>>>(gb, -1, nullptr);

    dim3 gVt(Bc * Hc, NTILES);
    vtile_k<<<gVt, DKc>>>();
    vscan_k<<<Bc * Hc, DKc>>>();

    dim3 gAttn(Sc / 64, Bc * Hc);       // (32, 32)
    attn_k<<<gAttn, 128, ATTN_SMEM>>>();

    dim3 gOut(Dc / 128, Mc / 128);      // (8, 32)
    gemm_k<<<gOut, 128, GEMM_SMEM>>>(gb, 3, out);
}

// round 15
// speedup vs baseline: 1.4718x; 1.0104x over previous
#include <cuda_runtime.h>
#include <cuda_bf16.h>
#include <cstdint>

// Problem constants
#define Bc 2
#define Sc 2048
#define Dc 1024
#define Hc 16
#define DKc 64
#define Mc (Bc*Sc)   // 4096
#define NTILES 32    // Sc / 64

// ---------------- scratch (no allocations allowed) ----------------
__device__ __nv_bfloat16 g_Xh[3][Mc*Dc];
__device__ __nv_bfloat16 g_Xl[3][Mc*Dc];
__device__ __nv_bfloat16 g_Wh[4][Dc*Dc];   // [k][n] as given
__device__ __nv_bfloat16 g_Wl[4][Dc*Dc];
__device__ __nv_bfloat16 g_Qh[Mc*Dc], g_Ql[Mc*Dc];
__device__ __nv_bfloat16 g_Kh[Mc*Dc], g_Kl[Mc*Dc];
__device__ __nv_bfloat16 g_Vh[Mc*Dc], g_Vl[Mc*Dc];
__device__ __nv_bfloat16 g_Ch[Mc*Dc], g_Cl[Mc*Dc];
__device__ float g_Vtile[Bc*Hc*NTILES*DKc];
__device__ float g_Vsuf[Bc*Hc*(NTILES+1)*DKc];
__device__ float g_pm[Bc*Sc];
__device__ int   g_mask_mode;

// ---------------- helpers ----------------
__device__ __forceinline__ uint32_t smem_u32(const void* p) {
    return (uint32_t)__cvta_generic_to_shared(p);
}

#define MMA(c, a, b0, b1)                                                     \
    asm volatile(                                                             \
        "mma.sync.aligned.m16n8k16.row.col.f32.bf16.bf16.f32 "                \
        "{%0,%1,%2,%3},{%4,%5,%6,%7},{%8,%9},{%0,%1,%2,%3};\n"                \
        : "+f"((c)[0]), "+f"((c)[1]), "+f"((c)[2]), "+f"((c)[3])              \
        : "r"((a)[0]), "r"((a)[1]), "r"((a)[2]), "r"((a)[3]),                 \
          "r"(b0), "r"(b1));

#define LDMX4(r, addr)                                                        \
    asm volatile("ldmatrix.sync.aligned.m8n8.x4.shared.b16 {%0,%1,%2,%3}, [%4];" \
        : "=r"((r)[0]), "=r"((r)[1]), "=r"((r)[2]), "=r"((r)[3]) : "r"(addr));

#define LDMX4T(r, addr)                                                       \
    asm volatile("ldmatrix.sync.aligned.m8n8.x4.trans.shared.b16 {%0,%1,%2,%3}, [%4];" \
        : "=r"((r)[0]), "=r"((r)[1]), "=r"((r)[2]), "=r"((r)[3]) : "r"(addr));

#define CPA16(dst, src)                                                       \
    asm volatile("cp.async.cg.shared.global [%0], [%1], 16;\n"                \
        :: "r"(dst), "l"(src));
#define CPA_COMMIT() asm volatile("cp.async.commit_group;\n" ::: "memory")
#define CPA_WAIT0()  asm volatile("cp.async.wait_group 0;\n" ::: "memory")
#define CPA_WAIT1()  asm volatile("cp.async.wait_group 1;\n" ::: "memory")

__device__ __forceinline__ uint32_t packh2(float a, float b) {
    __nv_bfloat162 t;
    t.x = __float2bfloat16(a);
    t.y = __float2bfloat16(b);
    return *reinterpret_cast<uint32_t*>(&t);
}
__device__ __forceinline__ uint32_t packl2(float a, float b) {
    float ra = a - __bfloat162float(__float2bfloat16(a));
    float rb = b - __bfloat162float(__float2bfloat16(b));
    return packh2(ra, rb);
}

// ---------------- padding-mask dtype sniffing ----------------
__global__ void detect_mask_k(const unsigned int* __restrict__ mm) {
    __shared__ int okInt, okFloat;
    if (threadIdx.x == 0) { okInt = 1; okFloat = 1; }
    __syncthreads();
    for (int i = threadIdx.x; i < 1024; i += blockDim.x) {
        unsigned int v = mm[i];
        if (v > 1u) okInt = 0;
        if (v != 0u && v != 0x3F800000u) okFloat = 0;
    }
    __syncthreads();
    if (threadIdx.x == 0)
        g_mask_mode = okInt ? 1 : (okFloat ? 2 : 0);
}

__global__ void expand_mask_k(const void* __restrict__ mraw) {
    int i = blockIdx.x * blockDim.x + threadIdx.x;
    if (i >= Bc * Sc) return;
    int mode = g_mask_mode;
    float v;
    if (mode == 1)       v = (((const int*)mraw)[i] != 0) ? 1.f : 0.f;
    else if (mode == 2)  v = (((const float*)mraw)[i] != 0.f) ? 1.f : 0.f;
    else                 v = (((const unsigned char*)mraw)[i] != 0) ? 1.f : 0.f;
    g_pm[i] = v;
}

// ---------------- fp32 -> bf16 hi/lo split (all 7 tensors, one launch) ----------------
struct SplitArgs { const float* src[7]; };

__global__ void split_all_k(SplitArgs sa) {
    const int id = blockIdx.y;
    const int n4 = (id < 3) ? (Mc * Dc / 4) : (Dc * Dc / 4);
    int i = blockIdx.x * blockDim.x + threadIdx.x;
    if (i >= n4) return;
    __nv_bfloat16 *ph, *pl;
    if (id < 3) { ph = g_Xh[id]; pl = g_Xl[id]; }
    else        { ph = g_Wh[id - 3]; pl = g_Wl[id - 3]; }
    float4 v = ((const float4*)sa.src[id])[i];
    float a[4] = {v.x, v.y, v.z, v.w};
    __nv_bfloat162 h0, h1, l0, l1;
    h0.x = __float2bfloat16(a[0]); h0.y = __float2bfloat16(a[1]);
    h1.x = __float2bfloat16(a[2]); h1.y = __float2bfloat16(a[3]);
    l0.x = __float2bfloat16(a[0] - __bfloat162float(h0.x));
    l0.y = __float2bfloat16(a[1] - __bfloat162float(h0.y));
    l1.x = __float2bfloat16(a[2] - __bfloat162float(h1.x));
    l1.y = __float2bfloat16(a[3] - __bfloat162float(h1.y));
    ((__nv_bfloat162*)ph)[i * 2]     = h0;
    ((__nv_bfloat162*)ph)[i * 2 + 1] = h1;
    ((__nv_bfloat162*)pl)[i * 2]     = l0;
    ((__nv_bfloat162*)pl)[i * 2 + 1] = l1;
}

// ---------------- V tile sums + suffix scan (parallel) ----------------
__global__ void vtile_k() {
    const int bh = blockIdx.x, t = blockIdx.y, dk = threadIdx.x;
    const size_t base = (size_t)bh * Sc * DKc + (size_t)t * 64 * DKc + dk;
    float s = 0.f;
#pragma unroll 8
    for (int j = 0; j < 64; j++) {
        size_t idx = base + (size_t)j * DKc;
        s += __bfloat162float(g_Vh[idx]) + __bfloat162float(g_Vl[idx]);
    }
    g_Vtile[((size_t)bh * NTILES + t) * DKc + dk] = s;
}

__global__ void vscan_k() {
    const int bh = blockIdx.x, dk = threadIdx.x;
    float acc = 0.f;
    float* out = g_Vsuf + (size_t)bh * (NTILES + 1) * DKc + dk;
    out[NTILES * DKc] = 0.f;
    for (int t = NTILES - 1; t >= 0; t--) {
        acc += g_Vtile[((size_t)bh * NTILES + t) * DKc + dk];
        out[t * DKc] = acc;
    }
}

// ---------------- bf16 split-GEMM: 128x128x32, 4 warps (2x2), 64x64 warp tile ----------
// cp.async 2-stage. MMAs reordered so same-acc distance = 8 (HMMA latency hiding).
struct GemmBias { const float* b[4]; };

#define ASTR 40
#define BSTR 136
#define A_ELE (128*ASTR)
#define B_ELE (32*BSTR)
#define G_STAGE (2*A_ELE + 2*B_ELE)
#define GEMM_SMEM (2*G_STAGE*2)          // 75776 bytes

__global__ __launch_bounds__(128, 2) void gemm_k(GemmBias gb, int mode_in, float* Cf) {
    extern __shared__ __align__(16) __nv_bfloat16 dsm[];
    const int mode = (mode_in < 0) ? (int)blockIdx.z : mode_in;
    const __nv_bfloat16 *Ah, *Al, *Bh, *Bl;
    __nv_bfloat16 *Oh = nullptr, *Ol = nullptr;
    if (mode < 3) {
        Ah = g_Xh[mode]; Al = g_Xl[mode];
        Bh = g_Wh[mode]; Bl = g_Wl[mode];
        Oh = (mode == 0) ? g_Qh : (mode == 1) ? g_Kh : g_Vh;
        Ol = (mode == 0) ? g_Ql : (mode == 1) ? g_Kl : g_Vl;
    } else {
        Ah = g_Ch; Al = g_Cl; Bh = g_Wh[3]; Bl = g_Wl[3];
    }
    const float* bias = gb.b[mode];

    const int tid = threadIdx.x;
    const int lane = tid & 31;
    const int wid = tid >> 5;              // 0..3
    const int wm = wid >> 1, wn = wid & 1; // 2 x 2 warp grid, 64x64 tiles
    const int g = lane >> 2, tg = lane & 3;
    const int sub = lane >> 3, rr = lane & 7;
    const int mBase = blockIdx.y * 128, nBase = blockIdx.x * 128;

#define GEMM_ISSUE(kb, s)                                                      \
    {                                                                          \
        __nv_bfloat16* stg = dsm + (s) * G_STAGE;                              \
        _Pragma("unroll")                                                      \
        for (int i = 0; i < 4; i++) {                                          \
            int c = tid + 128 * i;                                             \
            int ar = c >> 2, ac = (c & 3) * 8;                                 \
            size_t aoff = (size_t)(mBase + ar) * Dc + (kb) * 32 + ac;          \
            CPA16(smem_u32(stg + ar * ASTR + ac), Ah + aoff);                  \
            CPA16(smem_u32(stg + A_ELE + ar * ASTR + ac), Al + aoff);          \
            int br = c >> 4, bc = (c & 15) * 8;                                \
            size_t boff = (size_t)((kb) * 32 + br) * Dc + nBase + bc;          \
            CPA16(smem_u32(stg + 2*A_ELE + br * BSTR + bc), Bh + boff);        \
            CPA16(smem_u32(stg + 2*A_ELE + B_ELE + br * BSTR + bc), Bl + boff);\
        }                                                                      \
        CPA_COMMIT();                                                          \
    }

    float acc[4][8][4];
#pragma unroll
    for (int i = 0; i < 4; i++)
#pragma unroll
        for (int j = 0; j < 8; j++)
#pragma unroll
            for (int k = 0; k < 4; k++) acc[i][j][k] = 0.f;

    GEMM_ISSUE(0, 0);

    const int KIT = Dc / 32;   // 32
    for (int kb = 0; kb < KIT; kb++) {
        const int st = kb & 1;
        if (kb + 1 < KIT) { GEMM_ISSUE(kb + 1, st ^ 1); CPA_WAIT1(); }
        else              { CPA_WAIT0(); }
        __syncthreads();

        const __nv_bfloat16* pAh = dsm + st * G_STAGE;
        const __nv_bfloat16* pAl = pAh + A_ELE;
        const __nv_bfloat16* pBh = pAh + 2 * A_ELE;
        const __nv_bfloat16* pBl = pBh + B_ELE;

#pragma unroll
        for (int ks = 0; ks < 2; ks++) {
            uint32_t fah[4][4], fal[4][4];
#pragma unroll
            for (int mf = 0; mf < 4; mf++) {
                int ar = wm * 64 + mf * 16 + (sub & 1) * 8 + rr;
                int ac = ks * 16 + (sub >> 1) * 8;
                LDMX4(fah[mf], smem_u32(pAh + ar * ASTR + ac));
                LDMX4(fal[mf], smem_u32(pAl + ar * ASTR + ac));
            }
#pragma unroll
            for (int nb = 0; nb < 4; nb++) {
                uint32_t bh_[4], bl_[4];
                int br = ks * 16 + (sub & 1) * 8 + rr;
                int bc = wn * 64 + nb * 16 + (sub >> 1) * 8;
                LDMX4T(bh_, smem_u32(pBh + br * BSTR + bc));
                LDMX4T(bl_, smem_u32(pBl + br * BSTR + bc));
                // term 1: Ah x Bh   (8 distinct accs back-to-back)
#pragma unroll
                for (int mf = 0; mf < 4; mf++) {
                    MMA(acc[mf][2*nb],     fah[mf], bh_[0], bh_[1]);
                    MMA(acc[mf][2*nb + 1], fah[mf], bh_[2], bh_[3]);
                }
                // term 2: Ah x Bl
#pragma unroll
                for (int mf = 0; mf < 4; mf++) {
                    MMA(acc[mf][2*nb],     fah[mf], bl_[0], bl_[1]);
                    MMA(acc[mf][2*nb + 1], fah[mf], bl_[2], bl_[3]);
                }
                // term 3: Al x Bh
#pragma unroll
                for (int mf = 0; mf < 4; mf++) {
                    MMA(acc[mf][2*nb],     fal[mf], bh_[0], bh_[1]);
                    MMA(acc[mf][2*nb + 1], fal[mf], bh_[2], bh_[3]);
                }
            }
        }
        __syncthreads();
    }

    // epilogue
#pragma unroll
    for (int mf = 0; mf < 4; mf++) {
        int r0 = mBase + wm * 64 + mf * 16 + g;
        int r1 = r0 + 8;
#pragma unroll
        for (int nf = 0; nf < 8; nf++) {
            int n = nBase + wn * 64 + nf * 8 + tg * 2;
            float bv0 = bias[n], bv1 = bias[n + 1];
            float v00 = acc[mf][nf][0] + bv0, v01 = acc[mf][nf][1] + bv1;
            float v10 = acc[mf][nf][2] + bv0, v11 = acc[mf][nf][3] + bv1;
            if (mode == 3) {
                *(float2*)(Cf + (size_t)r0 * Dc + n) = make_float2(v00, v01);
                *(float2*)(Cf + (size_t)r1 * Dc + n) = make_float2(v10, v11);
            } else {
                int h = n >> 6, dk = n & 63;
#pragma unroll
                for (int p = 0; p < 2; p++) {
                    int r = p ? r1 : r0;
                    float a0 = p ? v10 : v00, a1 = p ? v11 : v01;
                    int b = r >> 11, s = r & 2047;
                    size_t idx = (((size_t)(b * Hc + h)) * Sc + s) * DKc + dk;
                    *(uint32_t*)(Oh + idx) = packh2(a0, a1);
                    *(uint32_t*)(Ol + idx) = packl2(a0, a1);
                }
            }
        }
    }
}

// ---------------- tensor-core flash attention, cp.async 2-stage + suffix skip ----------------
// MMAs reordered: kb/tt outer, acc-index inner -> same-acc distance = 8.
#define AT_A 4608
#define AT_STAGE (4*AT_A)
#define AT_PMS_OFF (2*AT_STAGE)
#define ATTN_SMEM (2*AT_STAGE*2 + 2*64*4)   // 74240 bytes

__global__ __launch_bounds__(128) void attn_k() {
    extern __shared__ __align__(16) __nv_bfloat16 adsm[];
    float* pmsf = (float*)(adsm + AT_PMS_OFF);

    const int tid = threadIdx.x;
    const int lane = tid & 31;
    const int wid = tid >> 5;
    const int g = lane >> 2, tg = lane & 3;
    const int sub = lane >> 3, rr = lane & 7;
    const int bh = blockIdx.y, b = bh >> 4, h = bh & 15;
    const int qblk = (int)gridDim.x - 1 - (int)blockIdx.x;   // longest CTAs first
    const int q0 = qblk * 64;
    const int nT = qblk + 1;
    const size_t base = (size_t)bh * Sc * DKc;

#define ATTN_ISSUE(t, s)                                                       \
    {                                                                          \
        __nv_bfloat16* stg = adsm + (s) * AT_STAGE;                            \
        size_t tb = base + (size_t)((t) * 64) * DKc;                           \
        _Pragma("unroll")                                                      \
        for (int k2 = 0; k2 < 4; k2++) {                                       \
            int c = tid + k2 * 128;                                            \
            int row = c >> 3, col = (c & 7) * 8;                               \
            size_t off = tb + (size_t)row * DKc + col;                         \
            int d = row * 72 + col;                                            \
            CPA16(smem_u32(stg + d), g_Kh + off);                              \
            CPA16(smem_u32(stg + AT_A + d), g_Kl + off);                       \
            CPA16(smem_u32(stg + 2*AT_A + d), g_Vh + off);                     \
            CPA16(smem_u32(stg + 3*AT_A + d), g_Vl + off);                     \
        }                                                                      \
        if (tid < 16)                                                          \
            CPA16(smem_u32(pmsf + (s) * 64 + tid * 4),                         \
                  g_pm + b * Sc + (t) * 64 + tid * 4);                         \
        CPA_COMMIT();                                                          \
    }

    ATTN_ISSUE(0, 0);
    {
        __nv_bfloat16* qstg = adsm + AT_STAGE;
        for (int c = tid; c < 64 * 8; c += 128) {
            int row = c >> 3, col = (c & 7) * 8;
            size_t off = base + (size_t)(q0 + row) * DKc + col;
            *(uint4*)(qstg + row * 72 + col)        = *(const uint4*)(g_Qh + off);
            *(uint4*)(qstg + AT_A + row * 72 + col) = *(const uint4*)(g_Ql + off);
        }
    }
    __syncthreads();
    uint32_t qh[4][4], ql[4][4];
    {
        const __nv_bfloat16* qstg = adsm + AT_STAGE;
#pragma unroll
        for (int kb = 0; kb < 4; kb++) {
            int arow = wid * 16 + (sub & 1) * 8 + rr;
            int acol = kb * 16 + (sub >> 1) * 8;
            LDMX4(qh[kb], smem_u32(qstg + arow * 72 + acol));
            LDMX4(ql[kb], smem_u32(qstg + AT_A + arow * 72 + acol));
        }
    }
    __syncthreads();   // Q extraction done before tile-1 cp.async overwrites stage 1

    float o[8][4];
#pragma unroll
    for (int i = 0; i < 8; i++)
#pragma unroll
        for (int k = 0; k < 4; k++) o[i][k] = 0.f;
    float sum0 = 0.f, sum1 = 0.f;
    const int row0 = q0 + wid * 16 + g, row1 = row0 + 8;

    for (int t = 0; t < nT; t++) {
        const int st = t & 1;
        const int kv0 = t * 64;
        if (t + 1 < nT) { ATTN_ISSUE(t + 1, st ^ 1); CPA_WAIT1(); }
        else            { CPA_WAIT0(); }
        __syncthreads();

        const __nv_bfloat16* sKh = adsm + st * AT_STAGE;
        const __nv_bfloat16* sKl = sKh + AT_A;
        const __nv_bfloat16* sVh = sKh + 2 * AT_A;
        const __nv_bfloat16* sVl = sKh + 3 * AT_A;
        const float* pms = pmsf + st * 64;

        // S = Q K^T  (split, 3-term) — kb outer, jj inner (acc distance 8)
        float s[8][4];
#pragma unroll
        for (int i = 0; i < 8; i++)
#pragma unroll
            for (int k = 0; k < 4; k++) s[i][k] = 0.f;
#pragma unroll
        for (int kb = 0; kb < 4; kb++) {
            uint32_t bKh[4][4], bKl[4][4];
#pragma unroll
            for (int jj = 0; jj < 4; jj++) {
                int krow = jj * 16 + (sub >> 1) * 8 + rr;
                int kcol = kb * 16 + (sub & 1) * 8;
                LDMX4(bKh[jj], smem_u32(sKh + krow * 72 + kcol));
                LDMX4(bKl[jj], smem_u32(sKl + krow * 72 + kcol));
            }
            // term 1: qh x Kh
#pragma unroll
            for (int jj = 0; jj < 4; jj++) {
                MMA(s[2*jj],     qh[kb], bKh[jj][0], bKh[jj][1]);
                MMA(s[2*jj + 1], qh[kb], bKh[jj][2], bKh[jj][3]);
            }
            // term 2: qh x Kl
#pragma unroll
            for (int jj = 0; jj < 4; jj++) {
                MMA(s[2*jj],     qh[kb], bKl[jj][0], bKl[jj][1]);
                MMA(s[2*jj + 1], qh[kb], bKl[jj][2], bKl[jj][3]);
            }
            // term 3: ql x Kh
#pragma unroll
            for (int jj = 0; jj < 4; jj++) {
                MMA(s[2*jj],     ql[kb], bKh[jj][0], bKh[jj][1]);
                MMA(s[2*jj + 1], ql[kb], bKh[jj][2], bKh[jj][3]);
            }
        }

        // mask + exp, re-pack as P A-fragments
        uint32_t ph[4][4], pl[4][4];
#pragma unroll
        for (int j = 0; j < 8; j++) {
            int cg = kv0 + j * 8 + tg * 2;
            float2 mv = *(float2*)&pms[j * 8 + tg * 2];
            float sc0 = (cg     > row0 || mv.x != 0.f) ? 1e-10f : s[j][0] * 0.125f;
            float sc1 = (cg + 1 > row0 || mv.y != 0.f) ? 1e-10f : s[j][1] * 0.125f;
            float sc2 = (cg     > row1 || mv.x != 0.f) ? 1e-10f : s[j][2] * 0.125f;
            float sc3 = (cg + 1 > row1 || mv.y != 0.f) ? 1e-10f : s[j][3] * 0.125f;
            float e0 = __expf(sc0), e1 = __expf(sc1);
            float e2 = __expf(sc2), e3 = __expf(sc3);
            sum0 += e0 + e1;
            sum1 += e2 + e3;
            int tt = j >> 1;
            if ((j & 1) == 0) {
                ph[tt][0] = packh2(e0, e1); ph[tt][1] = packh2(e2, e3);
                pl[tt][0] = packl2(e0, e1); pl[tt][1] = packl2(e2, e3);
            } else {
                ph[tt][2] = packh2(e0, e1); ph[tt][3] = packh2(e2, e3);
                pl[tt][2] = packl2(e0, e1); pl[tt][3] = packl2(e2, e3);
            }
        }

        // O += P V  (split, 3-term) — tt outer, dd inner (acc distance 8)
#pragma unroll
        for (int tt = 0; tt < 4; tt++) {
            uint32_t vh_[4][4], vl_[4][4];
#pragma unroll
            for (int dd = 0; dd < 4; dd++) {
                int vrow = tt * 16 + (sub & 1) * 8 + rr;
                int vcol = dd * 16 + (sub >> 1) * 8;
                LDMX4T(vh_[dd], smem_u32(sVh + vrow * 72 + vcol));
                LDMX4T(vl_[dd], smem_u32(sVl + vrow * 72 + vcol));
            }
            // term 1: ph x Vh
#pragma unroll
            for (int dd = 0; dd < 4; dd++) {
                MMA(o[2*dd],     ph[tt], vh_[dd][0], vh_[dd][1]);
                MMA(o[2*dd + 1], ph[tt], vh_[dd][2], vh_[dd][3]);
            }
            // term 2: ph x Vl
#pragma unroll
            for (int dd = 0; dd < 4; dd++) {
                MMA(o[2*dd],     ph[tt], vl_[dd][0], vl_[dd][1]);
                MMA(o[2*dd + 1], ph[tt], vl_[dd][2], vl_[dd][3]);
            }
            // term 3: pl x Vh
#pragma unroll
            for (int dd = 0; dd < 4; dd++) {
                MMA(o[2*dd],     pl[tt], vh_[dd][0], vh_[dd][1]);
                MMA(o[2*dd + 1], pl[tt], vh_[dd][2], vh_[dd][3]);
            }
        }
        __syncthreads();
    }

    // future keys: per-lane-owned o elements get the fp32 suffix sum
    {
        const float* suf = g_Vsuf + ((size_t)bh * (NTILES + 1) + nT) * DKc;
#pragma unroll
        for (int nf = 0; nf < 8; nf++) {
            int col = nf * 8 + tg * 2;
            float vA = suf[col], vB = suf[col + 1];
            o[nf][0] += vA; o[nf][1] += vB;
            o[nf][2] += vA; o[nf][3] += vB;
        }
    }

    sum0 += __shfl_xor_sync(0xFFFFFFFFu, sum0, 1);
    sum0 += __shfl_xor_sync(0xFFFFFFFFu, sum0, 2);
    sum1 += __shfl_xor_sync(0xFFFFFFFFu, sum1, 1);
    sum1 += __shfl_xor_sync(0xFFFFFFFFu, sum1, 2);
    const float cnt = (float)(Sc - nT * 64);
    sum0 += cnt;
    sum1 += cnt;
    float inv0 = 1.f / sum0, inv1 = 1.f / sum1;

#pragma unroll
    for (int nf = 0; nf < 8; nf++) {
        int dk = nf * 8 + tg * 2;
        float v00 = o[nf][0] * inv0, v01 = o[nf][1] * inv0;
        float v10 = o[nf][2] * inv1, v11 = o[nf][3] * inv1;
        size_t i0 = ((size_t)(b * Sc + row0)) * Dc + h * DKc + dk;
        size_t i1 = ((size_t)(b * Sc + row1)) * Dc + h * DKc + dk;
        *(uint32_t*)(g_Ch + i0) = packh2(v00, v01);
        *(uint32_t*)(g_Cl + i0) = packl2(v00, v01);
        *(uint32_t*)(g_Ch + i1) = packh2(v10, v11);
        *(uint32_t*)(g_Cl + i1) = packl2(v10, v11);
    }
}

// ---------------- launch ----------------
extern "C" void kernel_launch(void* const* d_in, const int* in_sizes, int n_in,
                              void* d_out, int out_size) {
    const float* query = (const float*)d_in[0];
    const float* key   = (const float*)d_in[1];
    const float* value = (const float*)d_in[2];
    const void*  pmask = d_in[3];
    const float* Wq = (const float*)d_in[4];
    const float* bq = (const float*)d_in[5];
    const float* Wk = (const float*)d_in[6];
    const float* bk = (const float*)d_in[7];
    const float* Wv = (const float*)d_in[8];
    const float* bv = (const float*)d_in[9];
    const float* Wo = (const float*)d_in[10];
    const float* bo = (const float*)d_in[11];
    float* out = (float*)d_out;

    cudaFuncSetAttribute(gemm_k, cudaFuncAttributeMaxDynamicSharedMemorySize, GEMM_SMEM);
    cudaFuncSetAttribute(attn_k, cudaFuncAttributeMaxDynamicSharedMemorySize, ATTN_SMEM);

    detect_mask_k<<<1, 256>>>((const unsigned int*)pmask);
    expand_mask_k<<<(Bc * Sc + 255) / 256, 256>>>(pmask);

    SplitArgs sa;
    sa.src[0] = query; sa.src[1] = key; sa.src[2] = value;
    sa.src[3] = Wq; sa.src[4] = Wk; sa.src[5] = Wv; sa.src[6] = Wo;
    const int nAct4 = Mc * Dc / 4;
    dim3 gSplit((nAct4 + 255) / 256, 7);
    split_all_k<<<gSplit, 256>>>(sa);

    GemmBias gb;
    gb.b[0] = bq; gb.b[1] = bk; gb.b[2] = bv; gb.b[3] = bo;

    dim3 gQKV(Dc / 128, Mc / 128, 3);   // (8, 32, 3)
    gemm_k<<<gQKV, 128, GEMM_SMEM>>>(gb, -1, nullptr);

    dim3 gVt(Bc * Hc, NTILES);
    vtile_k<<<gVt, DKc>>>();
    vscan_k<<<Bc * Hc, DKc>>>();

    dim3 gAttn(Sc / 64, Bc * Hc);       // (32, 32)
    attn_k<<<gAttn, 128, ATTN_SMEM>>>();

    dim3 gOut(Dc / 128, Mc / 128);      // (8, 32)
    gemm_k<<<gOut, 128, GEMM_SMEM>>>(gb, 3, out);
}